// round 12
// baseline (speedup 1.0000x reference)
#include <cuda_runtime.h>
#include <cuda_bf16.h>
#include <cuda_fp16.h>
#include <cstdint>

#define N_NODES 100000
#define E_MAX   1600000
#define HID     128
#define GBM 128

typedef unsigned long long u64t;
typedef unsigned int u32t;

// ---------------- device scratch (no allocations allowed) ----------------
__device__ int   g_deg[N_NODES];
__device__ int   g_rowptr[N_NODES + 1];
__device__ int   g_fill[N_NODES];
__device__ int   g_col[E_MAX];
__device__ float g_dinv[N_NODES];
__device__ float g_tx1[(size_t)N_NODES * HID];
__device__ float g_h1 [(size_t)N_NODES * HID];
__device__ u32t  g_hg [64 * HID];                    // float bits, atomicMax
__device__ u32t  g_Wbhi[2 * HID * HID];
__device__ u32t  g_Wblo[2 * HID * HID];
__device__ u32t  g_fh [(size_t)N_NODES * (HID / 2)]; // fp16 dinv-premultiplied features
// decoupled-lookback scan state (flags re-zeroed by k_fill each call)
__device__ volatile int g_incl[64];
__device__ volatile int g_flag[64];

// ---------------- helpers ----------------
__device__ __forceinline__ u32t pack_bf16(float lo_val, float hi_val) {
    u32t r;
    asm("cvt.rn.bf16x2.f32 %0, %1, %2;" : "=r"(r) : "f"(hi_val), "f"(lo_val));
    return r;
}
__device__ __forceinline__ void mma_bf16(float* c, const u32t* a, const u32t* b) {
    asm volatile("mma.sync.aligned.m16n8k16.row.col.f32.bf16.bf16.f32 "
        "{%0,%1,%2,%3}, {%4,%5,%6,%7}, {%8,%9}, {%0,%1,%2,%3};"
        : "+f"(c[0]), "+f"(c[1]), "+f"(c[2]), "+f"(c[3])
        : "r"(a[0]), "r"(a[1]), "r"(a[2]), "r"(a[3]), "r"(b[0]), "r"(b[1]));
}

// ---------------- 1. hist + W prep + zero g_hg ----------------
__global__ void k_hist(const int* __restrict__ dst,
                       const float* __restrict__ W1, const float* __restrict__ W2, int e) {
    int i = blockIdx.x * 256 + threadIdx.x;
    if (i < e) atomicAdd(&g_deg[dst[i]], 1);
    if (i < 32768) {
        int l  = i >> 14;
        int r  = i & 16383;
        int nn = r >> 7;
        int k2 = r & 127;
        const float* Wl = l ? W2 : W1;
        float v0 = Wl[(size_t)(2 * k2) * HID + nn];
        float v1 = Wl[(size_t)(2 * k2 + 1) * HID + nn];
        __nv_bfloat16 h0 = __float2bfloat16_rn(v0);
        __nv_bfloat16 h1 = __float2bfloat16_rn(v1);
        float l0 = v0 - __bfloat162float(h0);
        float l1 = v1 - __bfloat162float(h1);
        int o = l * (HID * HID) + nn * 128 + k2;
        g_Wbhi[o] = pack_bf16(__bfloat162float(h0), __bfloat162float(h1));
        g_Wblo[o] = pack_bf16(l0, l1);
    }
    if (i < 64 * HID) g_hg[i] = 0u;
}

// ---------------- 2. multi-block scan: decoupled lookback ----------------
// grid = ceil(n/4096) blocks x 1024 threads, 4 elems/thread.
__global__ void k_scan(int n, int e) {
    __shared__ int wsum[32];
    __shared__ int sprefix;
    int bid = blockIdx.x;
    int t = threadIdx.x;
    int lane = t & 31;
    int wid  = t >> 5;
    int i0 = bid * 4096 + t * 4;

    int4 d = make_int4(0, 0, 0, 0);
    if (i0 + 3 < n) d = *(const int4*)&g_deg[i0];
    else if (i0 < n) {
        d.x = g_deg[i0];
        if (i0 + 1 < n) d.y = g_deg[i0 + 1];
        if (i0 + 2 < n) d.z = g_deg[i0 + 2];
    }
    int s4 = d.x + d.y + d.z + d.w;
    int v = s4;
#pragma unroll
    for (int o = 1; o < 32; o <<= 1) {
        int x = __shfl_up_sync(0xffffffffu, v, o);
        if (lane >= o) v += x;
    }
    if (lane == 31) wsum[wid] = v;
    __syncthreads();
    if (wid == 0) {
        int w = wsum[lane];
#pragma unroll
        for (int o = 1; o < 32; o <<= 1) {
            int x = __shfl_up_sync(0xffffffffu, w, o);
            if (lane >= o) w += x;
        }
        wsum[lane] = w;
    }
    __syncthreads();
    int excl  = (wid ? wsum[wid - 1] : 0) + (v - s4);
    int total = wsum[31];

    if (t == 0) {
        int p = 0;
        if (bid > 0) {
            while (g_flag[bid - 1] == 0) { }
            p = g_incl[bid - 1];
        }
        g_incl[bid] = p + total;
        __threadfence();
        g_flag[bid] = 1;
        sprefix = p;
    }
    __syncthreads();

    int run = excl + sprefix;
    if (i0 < n) {
        g_rowptr[i0] = run; g_fill[i0] = run;
        g_dinv[i0] = rsqrtf(fmaxf((float)d.x, 1.0f)); run += d.x;
        if (i0 + 1 < n) { g_rowptr[i0+1] = run; g_fill[i0+1] = run;
            g_dinv[i0+1] = rsqrtf(fmaxf((float)d.y, 1.0f)); run += d.y; }
        if (i0 + 2 < n) { g_rowptr[i0+2] = run; g_fill[i0+2] = run;
            g_dinv[i0+2] = rsqrtf(fmaxf((float)d.z, 1.0f)); run += d.z; }
        if (i0 + 3 < n) { g_rowptr[i0+3] = run; g_fill[i0+3] = run;
            g_dinv[i0+3] = rsqrtf(fmaxf((float)d.w, 1.0f)); }
    }
    if (bid == gridDim.x - 1 && t == 0) g_rowptr[n] = e;
}

// ---------------- 3. CSR fill + tohalf(layer0) + zero deg + zero scan flags ----------------
__global__ void k_fill(const int* __restrict__ src, const int* __restrict__ dst,
                       const float* __restrict__ xin, int e, int n) {
    int j = blockIdx.x * 256 + threadIdx.x;
    if (j < e) {
        int p = atomicAdd(&g_fill[dst[j]], 1);
        g_col[p] = src[j];
    }
    if (j < n * 32) {
        int row = j >> 5;
        int q   = j & 31;
        float4 v = *(const float4*)&xin[(size_t)row * HID + q * 4];
        float w = g_dinv[row];
        __half2 a = __floats2half2_rn(v.x * w, v.y * w);
        __half2 b = __floats2half2_rn(v.z * w, v.w * w);
        uint2 o = make_uint2(*(u32t*)&a, *(u32t*)&b);
        *(uint2*)&g_fh[(size_t)row * (HID / 2) + q * 2] = o;
    }
    if (j < n) g_deg[j] = 0;     // ready for next call (first call: static zero)
    if (j < 64) g_flag[j] = 0;   // reset scan lookback flags for next call
}

// ---------------- 4/6. SpMM: fp16 gather, fp32 accumulate ----------------
__global__ void k_spmm(int n) {
    int row = blockIdx.x * 8 + (threadIdx.x >> 5);
    if (row >= n) return;
    int lane = threadIdx.x & 31;
    int e0 = g_rowptr[row];
    int e1 = g_rowptr[row + 1];
    int co = lane * 2;
    float4 acc0 = make_float4(0.f, 0.f, 0.f, 0.f);
    float4 acc1 = make_float4(0.f, 0.f, 0.f, 0.f);
    int e = e0;
    for (; e + 4 <= e1; e += 4) {
        int s0 = g_col[e];
        int s1 = g_col[e + 1];
        int s2 = g_col[e + 2];
        int s3 = g_col[e + 3];
        uint2 f0 = *(const uint2*)&g_fh[(size_t)s0 * (HID / 2) + co];
        uint2 f1 = *(const uint2*)&g_fh[(size_t)s1 * (HID / 2) + co];
        uint2 f2 = *(const uint2*)&g_fh[(size_t)s2 * (HID / 2) + co];
        uint2 f3 = *(const uint2*)&g_fh[(size_t)s3 * (HID / 2) + co];
        float2 a0 = __half22float2(*(__half2*)&f0.x), b0 = __half22float2(*(__half2*)&f0.y);
        float2 a1 = __half22float2(*(__half2*)&f1.x), b1 = __half22float2(*(__half2*)&f1.y);
        float2 a2 = __half22float2(*(__half2*)&f2.x), b2 = __half22float2(*(__half2*)&f2.y);
        float2 a3 = __half22float2(*(__half2*)&f3.x), b3 = __half22float2(*(__half2*)&f3.y);
        acc0.x += a0.x; acc0.y += a0.y; acc0.z += b0.x; acc0.w += b0.y;
        acc1.x += a1.x; acc1.y += a1.y; acc1.z += b1.x; acc1.w += b1.y;
        acc0.x += a2.x; acc0.y += a2.y; acc0.z += b2.x; acc0.w += b2.y;
        acc1.x += a3.x; acc1.y += a3.y; acc1.z += b3.x; acc1.w += b3.y;
    }
    for (; e < e1; e++) {
        int s = g_col[e];
        uint2 f = *(const uint2*)&g_fh[(size_t)s * (HID / 2) + co];
        float2 a = __half22float2(*(__half2*)&f.x), b = __half22float2(*(__half2*)&f.y);
        acc0.x += a.x; acc0.y += a.y; acc0.z += b.x; acc0.w += b.y;
    }
    float sc = -g_dinv[row];
    float4 o;
    o.x = (acc0.x + acc1.x) * sc;
    o.y = (acc0.y + acc1.y) * sc;
    o.z = (acc0.z + acc1.z) * sc;
    o.w = (acc0.w + acc1.w) * sc;
    *(float4*)&g_tx1[(size_t)row * HID + lane * 4] = o;
}

// ---------------- 5/7. tensor GEMM + fused epilogues ----------------
// layer 0: writes g_h1 fp32 + g_fh (half, dinv-premult)
// layer 1: no C write; per-block segment max -> atomicMax into g_hg
__global__ __launch_bounds__(256, 2) void k_gemm_tc(int layer,
                                                    const float* __restrict__ xin,
                                                    const float* __restrict__ bias,
                                                    int n, int gsize, int nb) {
    const float* __restrict__ Afeat = (layer == 0) ? xin : g_h1;
    const u32t* __restrict__ Whi = &g_Wbhi[layer * (HID * HID)];
    const u32t* __restrict__ Wlo = &g_Wblo[layer * (HID * HID)];

    __shared__ u32t As_hi[2][GBM][8];
    __shared__ u32t As_lo[2][GBM][8];
    __shared__ u32t Ws_hi[2][HID][8];
    __shared__ u32t Ws_lo[2][HID][8];

    int tid  = threadIdx.x;
    int lane = tid & 31;
    int wid  = tid >> 5;
    int wm   = wid & 1;
    int wn   = wid >> 1;
    int lr   = lane >> 2;
    int lc   = lane & 3;
    int bm   = blockIdx.x * GBM;
    int swl  = lr & 6;
    int ca   = lc ^ swl;

    float acc[4][4][4];
#pragma unroll
    for (int mi = 0; mi < 4; mi++)
#pragma unroll
        for (int ni = 0; ni < 4; ni++)
#pragma unroll
            for (int q = 0; q < 4; q++) acc[mi][ni][q] = 0.f;

    int tr = tid >> 2;
    int tq = tid & 3;

    for (int kb = 0; kb < 8; kb++) {
        int kg = kb * 32;
        const float* __restrict__ A = (kg < HID) ? Afeat : g_tx1;
        int kcol = kg & (HID - 1);

#pragma unroll
        for (int h = 0; h < 2; h++) {
#pragma unroll
            for (int p = 0; p < 2; p++) {
                int rl = tr + p * 64;
                int sw = rl & 6;
                int cc = (tq * 2) ^ sw;
                int row = bm + rl;
                float4 v = make_float4(0.f, 0.f, 0.f, 0.f);
                if (row < n) v = *(const float4*)&A[(size_t)row * HID + kcol + h * 16 + tq * 4];
                __nv_bfloat16 bx = __float2bfloat16_rn(v.x);
                __nv_bfloat16 by = __float2bfloat16_rn(v.y);
                __nv_bfloat16 bz = __float2bfloat16_rn(v.z);
                __nv_bfloat16 bw = __float2bfloat16_rn(v.w);
                float fx = __bfloat162float(bx), fy = __bfloat162float(by);
                float fz = __bfloat162float(bz), fw = __bfloat162float(bw);
                uint2 hi = make_uint2(pack_bf16(fx, fy), pack_bf16(fz, fw));
                uint2 lo = make_uint2(pack_bf16(v.x - fx, v.y - fy),
                                      pack_bf16(v.z - fz, v.w - fw));
                *(uint2*)&As_hi[h][rl][cc] = hi;
                *(uint2*)&As_lo[h][rl][cc] = lo;
                int wo = rl * 128 + (kg + h * 16) / 2 + tq * 2;
                *(uint2*)&Ws_hi[h][rl][cc] = *(const uint2*)&Whi[wo];
                *(uint2*)&Ws_lo[h][rl][cc] = *(const uint2*)&Wlo[wo];
            }
        }
        __syncthreads();

#pragma unroll
        for (int h = 0; h < 2; h++) {
            u32t bh[4][2], bl[4][2];
#pragma unroll
            for (int ni = 0; ni < 4; ni++) {
                int n0 = wn * 32 + ni * 8 + lr;
                bh[ni][0] = Ws_hi[h][n0][ca];
                bh[ni][1] = Ws_hi[h][n0][ca ^ 4];
                bl[ni][0] = Ws_lo[h][n0][ca];
                bl[ni][1] = Ws_lo[h][n0][ca ^ 4];
            }
#pragma unroll
            for (int mi = 0; mi < 4; mi++) {
                int m0 = wm * 64 + mi * 16;
                u32t ah[4], al[4];
                ah[0] = As_hi[h][m0 + lr][ca];
                ah[1] = As_hi[h][m0 + lr + 8][ca];
                ah[2] = As_hi[h][m0 + lr][ca ^ 4];
                ah[3] = As_hi[h][m0 + lr + 8][ca ^ 4];
                al[0] = As_lo[h][m0 + lr][ca];
                al[1] = As_lo[h][m0 + lr + 8][ca];
                al[2] = As_lo[h][m0 + lr][ca ^ 4];
                al[3] = As_lo[h][m0 + lr + 8][ca ^ 4];
#pragma unroll
                for (int ni = 0; ni < 4; ni++) {
                    mma_bf16(acc[mi][ni], ah, bh[ni]);
                    mma_bf16(acc[mi][ni], ah, bl[ni]);
                    mma_bf16(acc[mi][ni], al, bh[ni]);
                }
            }
        }
        __syncthreads();
    }

    if (layer == 0) {
#pragma unroll
        for (int mi = 0; mi < 4; mi++) {
            int r0 = bm + wm * 64 + mi * 16 + lr;
            int r1 = r0 + 8;
            float w0 = (r0 < n) ? g_dinv[r0] : 0.f;
            float w1 = (r1 < n) ? g_dinv[r1] : 0.f;
#pragma unroll
            for (int ni = 0; ni < 4; ni++) {
                int col = wn * 32 + ni * 8 + lc * 2;
                float2 bv = *(const float2*)&bias[col];
                if (r0 < n) {
                    float v0 = fmaxf(acc[mi][ni][0] + bv.x, 0.f);
                    float v1 = fmaxf(acc[mi][ni][1] + bv.y, 0.f);
                    *(float2*)&g_h1[(size_t)r0 * HID + col] = make_float2(v0, v1);
                    __half2 hh = __floats2half2_rn(v0 * w0, v1 * w0);
                    g_fh[(size_t)r0 * (HID / 2) + (col >> 1)] = *(u32t*)&hh;
                }
                if (r1 < n) {
                    float v2 = fmaxf(acc[mi][ni][2] + bv.x, 0.f);
                    float v3 = fmaxf(acc[mi][ni][3] + bv.y, 0.f);
                    *(float2*)&g_h1[(size_t)r1 * HID + col] = make_float2(v2, v3);
                    __half2 hh = __floats2half2_rn(v2 * w1, v3 * w1);
                    g_fh[(size_t)r1 * (HID / 2) + (col >> 1)] = *(u32t*)&hh;
                }
            }
        }
    } else {
        u32t* red = &As_hi[0][0][0];       // reuse smem (256 u32)
        if (tid < 256) red[tid] = 0u;
        __syncthreads();
        int g0  = bm / gsize;
        int bnd = (g0 + 1) * gsize;
#pragma unroll
        for (int mi = 0; mi < 4; mi++) {
            int r0 = bm + wm * 64 + mi * 16 + lr;
            int r1 = r0 + 8;
#pragma unroll
            for (int ni = 0; ni < 4; ni++) {
                int col = wn * 32 + ni * 8 + lc * 2;
                float2 bv = *(const float2*)&bias[col];
                if (r0 < n) {
                    float v0 = fmaxf(acc[mi][ni][0] + bv.x, 0.f);
                    float v1 = fmaxf(acc[mi][ni][1] + bv.y, 0.f);
                    int s = (r0 >= bnd) ? 128 : 0;
                    atomicMax(&red[s + col], __float_as_uint(v0));
                    atomicMax(&red[s + col + 1], __float_as_uint(v1));
                }
                if (r1 < n) {
                    float v2 = fmaxf(acc[mi][ni][2] + bv.x, 0.f);
                    float v3 = fmaxf(acc[mi][ni][3] + bv.y, 0.f);
                    int s = (r1 >= bnd) ? 128 : 0;
                    atomicMax(&red[s + col], __float_as_uint(v2));
                    atomicMax(&red[s + col + 1], __float_as_uint(v3));
                }
            }
        }
        __syncthreads();
        if (tid < 256) {
            int seg = tid >> 7;
            int c   = tid & 127;
            int g   = g0 + seg;
            bool has = (seg == 0) || (bnd < bm + GBM && bnd < n);
            if (g < nb && has) atomicMax(&g_hg[g * HID + c], red[tid]);
        }
    }
}

// ---------------- 8. classifier head ----------------
__global__ void k_final(const float* __restrict__ Wc, const float* __restrict__ bc,
                        float* __restrict__ out, int nb) {
    int t = blockIdx.x * blockDim.x + threadIdx.x;
    if (t >= nb * 10) return;
    int g = t / 10;
    int c = t % 10;
    float acc = bc[c];
#pragma unroll 8
    for (int k = 0; k < HID; k++)
        acc += __uint_as_float(g_hg[g * HID + k]) * Wc[k * 10 + c];
    out[t] = acc;
}

// ---------------- launch ----------------
extern "C" void kernel_launch(void* const* d_in, const int* in_sizes, int n_in,
                              void* d_out, int out_size) {
    const float* x   = (const float*)d_in[0];
    const float* W1  = (const float*)d_in[1];
    const float* b1  = (const float*)d_in[2];
    const float* W2  = (const float*)d_in[3];
    const float* b2  = (const float*)d_in[4];
    const float* Wc  = (const float*)d_in[5];
    const float* bc  = (const float*)d_in[6];
    const int*   src = (const int*)d_in[7];
    const int*   dst = (const int*)d_in[8];
    float* out = (float*)d_out;

    int e = in_sizes[7];
    int n = in_sizes[9];
    int nb_graphs = out_size / 10;
    int gsize = n / nb_graphs;
    int nGemm = (n + GBM - 1) / GBM;
    int nScan = (n + 4095) / 4096;   // <= 64 (flag array bound)

    int histN = (e > 32768 ? e : 32768);
    int fillN = (e > n * 32 ? e : n * 32);

    k_hist<<<(histN + 255) / 256, 256>>>(dst, W1, W2, e);
    k_scan<<<nScan, 1024>>>(n, e);
    k_fill<<<(fillN + 255) / 256, 256>>>(src, dst, x, e, n);

    // layer 1
    k_spmm<<<(n + 7) / 8, 256>>>(n);
    k_gemm_tc<<<nGemm, 256>>>(0, x, b1, n, gsize, nb_graphs);
    // layer 2
    k_spmm<<<(n + 7) / 8, 256>>>(n);
    k_gemm_tc<<<nGemm, 256>>>(1, x, b2, n, gsize, nb_graphs);

    k_final<<<1, 512>>>(Wc, bc, out, nb_graphs);
}

// round 13
// speedup vs baseline: 1.3740x; 1.3740x over previous
#include <cuda_runtime.h>
#include <cuda_bf16.h>
#include <cuda_fp16.h>
#include <cstdint>

#define N_NODES 100000
#define E_MAX   1600000
#define HID     128
#define NB_SCAN 128
#define GBM 128

typedef unsigned long long u64t;
typedef unsigned int u32t;

// ---------------- device scratch (no allocations allowed) ----------------
__device__ int   g_deg[N_NODES];
__device__ int   g_rowptr[N_NODES + 1];
__device__ int   g_fill[N_NODES];
__device__ int   g_bsum[NB_SCAN];
__device__ int   g_boff[NB_SCAN];
__device__ int   g_col[E_MAX];
__device__ float g_dinv[N_NODES];
__device__ float g_tx1[(size_t)N_NODES * HID];
__device__ float g_h1 [(size_t)N_NODES * HID];
__device__ float g_h2 [(size_t)N_NODES * HID];
__device__ float g_hg [64 * HID];
__device__ u32t  g_Wbhi[2 * HID * HID];
__device__ u32t  g_Wblo[2 * HID * HID];
__device__ u32t  g_fh [(size_t)N_NODES * (HID / 2)];   // fp16 dinv-premultiplied features

// ---------------- helpers ----------------
__device__ __forceinline__ u32t pack_bf16(float lo_val, float hi_val) {
    u32t r;
    asm("cvt.rn.bf16x2.f32 %0, %1, %2;" : "=r"(r) : "f"(hi_val), "f"(lo_val));
    return r;
}
__device__ __forceinline__ void mma_bf16(float* c, const u32t* a, const u32t* b) {
    asm volatile("mma.sync.aligned.m16n8k16.row.col.f32.bf16.bf16.f32 "
        "{%0,%1,%2,%3}, {%4,%5,%6,%7}, {%8,%9}, {%0,%1,%2,%3};"
        : "+f"(c[0]), "+f"(c[1]), "+f"(c[2]), "+f"(c[3])
        : "r"(a[0]), "r"(a[1]), "r"(a[2]), "r"(a[3]), "r"(b[0]), "r"(b[1]));
}

// ---------------- 1. hist + W prep ----------------
__global__ void k_hist(const int* __restrict__ dst,
                       const float* __restrict__ W1, const float* __restrict__ W2, int e) {
    int i = blockIdx.x * 256 + threadIdx.x;
    if (i < e) atomicAdd(&g_deg[dst[i]], 1);
    if (i < 32768) {
        int l  = i >> 14;
        int r  = i & 16383;
        int nn = r >> 7;
        int k2 = r & 127;
        const float* Wl = l ? W2 : W1;
        float v0 = Wl[(size_t)(2 * k2) * HID + nn];
        float v1 = Wl[(size_t)(2 * k2 + 1) * HID + nn];
        __nv_bfloat16 h0 = __float2bfloat16_rn(v0);
        __nv_bfloat16 h1 = __float2bfloat16_rn(v1);
        float l0 = v0 - __bfloat162float(h0);
        float l1 = v1 - __bfloat162float(h1);
        int o = l * (HID * HID) + nn * 128 + k2;
        g_Wbhi[o] = pack_bf16(__bfloat162float(h0), __bfloat162float(h1));
        g_Wblo[o] = pack_bf16(l0, l1);
    }
}

// ---------------- 2-4. scan (round-10 proven 3-kernel version) ----------------
__global__ void k_scanA(int n) {
    __shared__ int s[1024];
    int tid = threadIdx.x;
    int i = blockIdx.x * 1024 + tid;
    int v = (i < n) ? g_deg[i] : 0;
    s[tid] = v;
    __syncthreads();
    for (int off = 1; off < 1024; off <<= 1) {
        int t = (tid >= off) ? s[tid - off] : 0;
        __syncthreads();
        s[tid] += t;
        __syncthreads();
    }
    if (i < n) g_rowptr[i] = s[tid] - v;
    if (tid == 1023) g_bsum[blockIdx.x] = s[1023];
}

__global__ void k_scanB(int nb) {
    __shared__ int s[NB_SCAN];
    int tid = threadIdx.x;
    int v = (tid < nb) ? g_bsum[tid] : 0;
    s[tid] = v;
    __syncthreads();
    for (int off = 1; off < NB_SCAN; off <<= 1) {
        int t = (tid >= off) ? s[tid - off] : 0;
        __syncthreads();
        s[tid] += t;
        __syncthreads();
    }
    s[tid] -= v;
    g_boff[tid] = s[tid];
}

__global__ void k_scanC(int n, int e) {
    int i = blockIdx.x * 1024 + threadIdx.x;
    if (i < n) {
        int rp = g_rowptr[i] + g_boff[i >> 10];
        g_rowptr[i] = rp;
        g_fill[i]   = rp;
        g_dinv[i]   = rsqrtf(fmaxf((float)g_deg[i], 1.0f));
        if (i == n - 1) g_rowptr[n] = e;
    }
}

// ---------------- 5. CSR fill + tohalf(layer0) + zero deg ----------------
__global__ void k_fill(const int* __restrict__ src, const int* __restrict__ dst,
                       const float* __restrict__ xin, int e, int n) {
    int j = blockIdx.x * 256 + threadIdx.x;
    if (j < e) {
        int p = atomicAdd(&g_fill[dst[j]], 1);
        g_col[p] = src[j];
    }
    if (j < n * 32) {
        int row = j >> 5;
        int q   = j & 31;
        float4 v = *(const float4*)&xin[(size_t)row * HID + q * 4];
        float w = g_dinv[row];
        __half2 a = __floats2half2_rn(v.x * w, v.y * w);
        __half2 b = __floats2half2_rn(v.z * w, v.w * w);
        uint2 o = make_uint2(*(u32t*)&a, *(u32t*)&b);
        *(uint2*)&g_fh[(size_t)row * (HID / 2) + q * 2] = o;
    }
    if (j < n) g_deg[j] = 0;   // ready for next call (first call: static zero)
}

// ---------------- tohalf (layer 1: g_h1 -> g_fh) ----------------
__global__ void k_tohalf(int n) {
    int idx = blockIdx.x * 256 + threadIdx.x;
    if (idx >= n * 32) return;
    int row = idx >> 5;
    int q   = idx & 31;
    float4 v = *(const float4*)&g_h1[(size_t)row * HID + q * 4];
    float w = g_dinv[row];
    __half2 a = __floats2half2_rn(v.x * w, v.y * w);
    __half2 b = __floats2half2_rn(v.z * w, v.w * w);
    uint2 o = make_uint2(*(u32t*)&a, *(u32t*)&b);
    *(uint2*)&g_fh[(size_t)row * (HID / 2) + q * 2] = o;
}

// ---------------- SpMM: fp16 gather, fp32 accumulate (round-10 proven) ----------------
__global__ void k_spmm(int n) {
    int row = blockIdx.x * 8 + (threadIdx.x >> 5);
    if (row >= n) return;
    int lane = threadIdx.x & 31;
    int e0 = g_rowptr[row];
    int e1 = g_rowptr[row + 1];
    int co = lane * 2;
    float4 acc0 = make_float4(0.f, 0.f, 0.f, 0.f);
    float4 acc1 = make_float4(0.f, 0.f, 0.f, 0.f);
    int e = e0;
    for (; e + 4 <= e1; e += 4) {
        int s0 = g_col[e];
        int s1 = g_col[e + 1];
        int s2 = g_col[e + 2];
        int s3 = g_col[e + 3];
        uint2 f0 = *(const uint2*)&g_fh[(size_t)s0 * (HID / 2) + co];
        uint2 f1 = *(const uint2*)&g_fh[(size_t)s1 * (HID / 2) + co];
        uint2 f2 = *(const uint2*)&g_fh[(size_t)s2 * (HID / 2) + co];
        uint2 f3 = *(const uint2*)&g_fh[(size_t)s3 * (HID / 2) + co];
        float2 a0 = __half22float2(*(__half2*)&f0.x), b0 = __half22float2(*(__half2*)&f0.y);
        float2 a1 = __half22float2(*(__half2*)&f1.x), b1 = __half22float2(*(__half2*)&f1.y);
        float2 a2 = __half22float2(*(__half2*)&f2.x), b2 = __half22float2(*(__half2*)&f2.y);
        float2 a3 = __half22float2(*(__half2*)&f3.x), b3 = __half22float2(*(__half2*)&f3.y);
        acc0.x += a0.x; acc0.y += a0.y; acc0.z += b0.x; acc0.w += b0.y;
        acc1.x += a1.x; acc1.y += a1.y; acc1.z += b1.x; acc1.w += b1.y;
        acc0.x += a2.x; acc0.y += a2.y; acc0.z += b2.x; acc0.w += b2.y;
        acc1.x += a3.x; acc1.y += a3.y; acc1.z += b3.x; acc1.w += b3.y;
    }
    for (; e < e1; e++) {
        int s = g_col[e];
        uint2 f = *(const uint2*)&g_fh[(size_t)s * (HID / 2) + co];
        float2 a = __half22float2(*(__half2*)&f.x), b = __half22float2(*(__half2*)&f.y);
        acc0.x += a.x; acc0.y += a.y; acc0.z += b.x; acc0.w += b.y;
    }
    float sc = -g_dinv[row];
    float4 o;
    o.x = (acc0.x + acc1.x) * sc;
    o.y = (acc0.y + acc1.y) * sc;
    o.z = (acc0.z + acc1.z) * sc;
    o.w = (acc0.w + acc1.w) * sc;
    *(float4*)&g_tx1[(size_t)row * HID + lane * 4] = o;
}

// ---------------- tensor GEMM (round-7/10 proven): C = relu([Afeat|g_tx1]@W + b) ----------------
__global__ __launch_bounds__(256, 2) void k_gemm_tc(int layer,
                                                    const float* __restrict__ xin,
                                                    const float* __restrict__ bias,
                                                    int n) {
    const float* __restrict__ Afeat = (layer == 0) ? xin : g_h1;
    float* __restrict__ C = (layer == 0) ? g_h1 : g_h2;
    const u32t* __restrict__ Whi = &g_Wbhi[layer * (HID * HID)];
    const u32t* __restrict__ Wlo = &g_Wblo[layer * (HID * HID)];

    __shared__ u32t As_hi[2][GBM][8];
    __shared__ u32t As_lo[2][GBM][8];
    __shared__ u32t Ws_hi[2][HID][8];
    __shared__ u32t Ws_lo[2][HID][8];

    int tid  = threadIdx.x;
    int lane = tid & 31;
    int wid  = tid >> 5;
    int wm   = wid & 1;
    int wn   = wid >> 1;
    int lr   = lane >> 2;
    int lc   = lane & 3;
    int bm   = blockIdx.x * GBM;
    int swl  = lr & 6;
    int ca   = lc ^ swl;

    float acc[4][4][4];
#pragma unroll
    for (int mi = 0; mi < 4; mi++)
#pragma unroll
        for (int ni = 0; ni < 4; ni++)
#pragma unroll
            for (int q = 0; q < 4; q++) acc[mi][ni][q] = 0.f;

    int tr = tid >> 2;
    int tq = tid & 3;

    for (int kb = 0; kb < 8; kb++) {
        int kg = kb * 32;
        const float* __restrict__ A = (kg < HID) ? Afeat : g_tx1;
        int kcol = kg & (HID - 1);

#pragma unroll
        for (int h = 0; h < 2; h++) {
#pragma unroll
            for (int p = 0; p < 2; p++) {
                int rl = tr + p * 64;
                int sw = rl & 6;
                int cc = (tq * 2) ^ sw;
                int row = bm + rl;
                float4 v = make_float4(0.f, 0.f, 0.f, 0.f);
                if (row < n) v = *(const float4*)&A[(size_t)row * HID + kcol + h * 16 + tq * 4];
                __nv_bfloat16 bx = __float2bfloat16_rn(v.x);
                __nv_bfloat16 by = __float2bfloat16_rn(v.y);
                __nv_bfloat16 bz = __float2bfloat16_rn(v.z);
                __nv_bfloat16 bw = __float2bfloat16_rn(v.w);
                float fx = __bfloat162float(bx), fy = __bfloat162float(by);
                float fz = __bfloat162float(bz), fw = __bfloat162float(bw);
                uint2 hi = make_uint2(pack_bf16(fx, fy), pack_bf16(fz, fw));
                uint2 lo = make_uint2(pack_bf16(v.x - fx, v.y - fy),
                                      pack_bf16(v.z - fz, v.w - fw));
                *(uint2*)&As_hi[h][rl][cc] = hi;
                *(uint2*)&As_lo[h][rl][cc] = lo;
                int wo = rl * 128 + (kg + h * 16) / 2 + tq * 2;
                *(uint2*)&Ws_hi[h][rl][cc] = *(const uint2*)&Whi[wo];
                *(uint2*)&Ws_lo[h][rl][cc] = *(const uint2*)&Wlo[wo];
            }
        }
        __syncthreads();

#pragma unroll
        for (int h = 0; h < 2; h++) {
            u32t bh[4][2], bl[4][2];
#pragma unroll
            for (int ni = 0; ni < 4; ni++) {
                int n0 = wn * 32 + ni * 8 + lr;
                bh[ni][0] = Ws_hi[h][n0][ca];
                bh[ni][1] = Ws_hi[h][n0][ca ^ 4];
                bl[ni][0] = Ws_lo[h][n0][ca];
                bl[ni][1] = Ws_lo[h][n0][ca ^ 4];
            }
#pragma unroll
            for (int mi = 0; mi < 4; mi++) {
                int m0 = wm * 64 + mi * 16;
                u32t ah[4], al[4];
                ah[0] = As_hi[h][m0 + lr][ca];
                ah[1] = As_hi[h][m0 + lr + 8][ca];
                ah[2] = As_hi[h][m0 + lr][ca ^ 4];
                ah[3] = As_hi[h][m0 + lr + 8][ca ^ 4];
                al[0] = As_lo[h][m0 + lr][ca];
                al[1] = As_lo[h][m0 + lr + 8][ca];
                al[2] = As_lo[h][m0 + lr][ca ^ 4];
                al[3] = As_lo[h][m0 + lr + 8][ca ^ 4];
#pragma unroll
                for (int ni = 0; ni < 4; ni++) {
                    mma_bf16(acc[mi][ni], ah, bh[ni]);
                    mma_bf16(acc[mi][ni], ah, bl[ni]);
                    mma_bf16(acc[mi][ni], al, bh[ni]);
                }
            }
        }
        __syncthreads();
    }

#pragma unroll
    for (int mi = 0; mi < 4; mi++) {
        int r0 = bm + wm * 64 + mi * 16 + lr;
        int r1 = r0 + 8;
#pragma unroll
        for (int ni = 0; ni < 4; ni++) {
            int col = wn * 32 + ni * 8 + lc * 2;
            float2 bv = *(const float2*)&bias[col];
            if (r0 < n) {
                float2 o;
                o.x = fmaxf(acc[mi][ni][0] + bv.x, 0.f);
                o.y = fmaxf(acc[mi][ni][1] + bv.y, 0.f);
                *(float2*)&C[(size_t)r0 * HID + col] = o;
            }
            if (r1 < n) {
                float2 o;
                o.x = fmaxf(acc[mi][ni][2] + bv.x, 0.f);
                o.y = fmaxf(acc[mi][ni][3] + bv.y, 0.f);
                *(float2*)&C[(size_t)r1 * HID + col] = o;
            }
        }
    }
}

// ---------------- segment max (round-10 proven) ----------------
__global__ void k_segmax(int gsize) {
    __shared__ float sm[8][HID];
    int g = blockIdx.x;
    int warp = threadIdx.x >> 5;
    int lane = threadIdx.x & 31;
    float4 m = make_float4(0.f, 0.f, 0.f, 0.f);
    int r0 = g * gsize;
    for (int r = r0 + warp; r < r0 + gsize; r += 8) {
        float4 v = *(const float4*)&g_h2[(size_t)r * HID + lane * 4];
        m.x = fmaxf(m.x, v.x);
        m.y = fmaxf(m.y, v.y);
        m.z = fmaxf(m.z, v.z);
        m.w = fmaxf(m.w, v.w);
    }
    *(float4*)&sm[warp][lane * 4] = m;
    __syncthreads();
    if (threadIdx.x < HID) {
        int f = threadIdx.x;
        float mm = sm[0][f];
#pragma unroll
        for (int w = 1; w < 8; w++) mm = fmaxf(mm, sm[w][f]);
        g_hg[g * HID + f] = mm;
    }
}

// ---------------- classifier head ----------------
__global__ void k_final(const float* __restrict__ Wc, const float* __restrict__ bc,
                        float* __restrict__ out, int nb) {
    int t = blockIdx.x * blockDim.x + threadIdx.x;
    if (t >= nb * 10) return;
    int g = t / 10;
    int c = t % 10;
    float acc = bc[c];
#pragma unroll 8
    for (int k = 0; k < HID; k++) acc += g_hg[g * HID + k] * Wc[k * 10 + c];
    out[t] = acc;
}

// ---------------- launch ----------------
extern "C" void kernel_launch(void* const* d_in, const int* in_sizes, int n_in,
                              void* d_out, int out_size) {
    const float* x   = (const float*)d_in[0];
    const float* W1  = (const float*)d_in[1];
    const float* b1  = (const float*)d_in[2];
    const float* W2  = (const float*)d_in[3];
    const float* b2  = (const float*)d_in[4];
    const float* Wc  = (const float*)d_in[5];
    const float* bc  = (const float*)d_in[6];
    const int*   src = (const int*)d_in[7];
    const int*   dst = (const int*)d_in[8];
    float* out = (float*)d_out;

    int e = in_sizes[7];
    int n = in_sizes[9];
    int nb_graphs = out_size / 10;
    int gsize = n / nb_graphs;
    int nbscan = (n + 1023) / 1024;
    int nGemm = (n + GBM - 1) / GBM;
    int nConv = (n * 32 + 255) / 256;

    int histN = (e > 32768 ? e : 32768);
    int fillN = (e > n * 32 ? e : n * 32);

    k_hist<<<(histN + 255) / 256, 256>>>(dst, W1, W2, e);
    k_scanA<<<nbscan, 1024>>>(n);
    k_scanB<<<1, NB_SCAN>>>(nbscan);
    k_scanC<<<nbscan, 1024>>>(n, e);
    k_fill<<<(fillN + 255) / 256, 256>>>(src, dst, x, e, n);

    // layer 1
    k_spmm<<<(n + 7) / 8, 256>>>(n);
    k_gemm_tc<<<nGemm, 256>>>(0, x, b1, n);
    // layer 2
    k_tohalf<<<nConv, 256>>>(n);
    k_spmm<<<(n + 7) / 8, 256>>>(n);
    k_gemm_tc<<<nGemm, 256>>>(1, x, b2, n);

    k_segmax<<<nb_graphs, 256>>>(gsize);
    k_final<<<1, 512>>>(Wc, bc, out, nb_graphs);
}

// round 14
// speedup vs baseline: 1.5938x; 1.1600x over previous
#include <cuda_runtime.h>
#include <cuda_fp16.h>
#include <cstdint>

#define N_NODES 100000
#define E_MAX   1600000
#define HID     128
#define NB_SCAN 128
#define GBM 128

typedef unsigned long long u64t;
typedef unsigned int u32t;

// ---------------- device scratch (no allocations allowed) ----------------
__device__ int   g_deg[N_NODES];
__device__ int   g_rowptr[N_NODES + 1];
__device__ int   g_fill[N_NODES];
__device__ int   g_bsum[NB_SCAN];
__device__ int   g_boff[NB_SCAN];
__device__ int   g_col[E_MAX];
__device__ float g_dinv[N_NODES];
__device__ float g_tx1[(size_t)N_NODES * HID];
__device__ float g_h2 [(size_t)N_NODES * HID];
__device__ float g_hg [64 * HID];
__device__ u32t  g_Wfhi[2 * HID * HID];                // fp16 pairs, W transposed [n][k/2]
__device__ u32t  g_Wflo[2 * HID * HID];
__device__ u32t  g_fh [(size_t)N_NODES * (HID / 2)];   // fp16 dinv-premultiplied features

// ---------------- helpers ----------------
__device__ __forceinline__ void mma_f16(float* c, const u32t* a, const u32t* b) {
    asm volatile("mma.sync.aligned.m16n8k16.row.col.f32.f16.f16.f32 "
        "{%0,%1,%2,%3}, {%4,%5,%6,%7}, {%8,%9}, {%0,%1,%2,%3};"
        : "+f"(c[0]), "+f"(c[1]), "+f"(c[2]), "+f"(c[3])
        : "r"(a[0]), "r"(a[1]), "r"(a[2]), "r"(a[3]), "r"(b[0]), "r"(b[1]));
}

// ---------------- 1. hist + W prep (fp16 hi/lo) ----------------
__global__ void k_hist(const int* __restrict__ dst,
                       const float* __restrict__ W1, const float* __restrict__ W2, int e) {
    int i = blockIdx.x * 256 + threadIdx.x;
    if (i < e) atomicAdd(&g_deg[dst[i]], 1);
    if (i < 32768) {
        int l  = i >> 14;
        int r  = i & 16383;
        int nn = r >> 7;
        int k2 = r & 127;
        const float* Wl = l ? W2 : W1;
        float v0 = Wl[(size_t)(2 * k2) * HID + nn];
        float v1 = Wl[(size_t)(2 * k2 + 1) * HID + nn];
        __half h0 = __float2half_rn(v0);
        __half h1 = __float2half_rn(v1);
        float l0 = v0 - __half2float(h0);
        float l1 = v1 - __half2float(h1);
        int o = l * (HID * HID) + nn * 128 + k2;
        __half2 HH = __halves2half2(h0, h1);
        __half2 LL = __floats2half2_rn(l0, l1);
        g_Wfhi[o] = *(u32t*)&HH;
        g_Wflo[o] = *(u32t*)&LL;
    }
}

// ---------------- 2-4. scan (round-10/13 proven) ----------------
__global__ void k_scanA(int n) {
    __shared__ int s[1024];
    int tid = threadIdx.x;
    int i = blockIdx.x * 1024 + tid;
    int v = (i < n) ? g_deg[i] : 0;
    s[tid] = v;
    __syncthreads();
    for (int off = 1; off < 1024; off <<= 1) {
        int t = (tid >= off) ? s[tid - off] : 0;
        __syncthreads();
        s[tid] += t;
        __syncthreads();
    }
    if (i < n) g_rowptr[i] = s[tid] - v;
    if (tid == 1023) g_bsum[blockIdx.x] = s[1023];
}

__global__ void k_scanB(int nb) {
    __shared__ int s[NB_SCAN];
    int tid = threadIdx.x;
    int v = (tid < nb) ? g_bsum[tid] : 0;
    s[tid] = v;
    __syncthreads();
    for (int off = 1; off < NB_SCAN; off <<= 1) {
        int t = (tid >= off) ? s[tid - off] : 0;
        __syncthreads();
        s[tid] += t;
        __syncthreads();
    }
    s[tid] -= v;
    g_boff[tid] = s[tid];
}

__global__ void k_scanC(int n, int e) {
    int i = blockIdx.x * 1024 + threadIdx.x;
    if (i < n) {
        int rp = g_rowptr[i] + g_boff[i >> 10];
        g_rowptr[i] = rp;
        g_fill[i]   = rp;
        g_dinv[i]   = rsqrtf(fmaxf((float)g_deg[i], 1.0f));
        if (i == n - 1) g_rowptr[n] = e;
    }
}

// ---------------- 5. CSR fill + tohalf(x) + zero deg ----------------
__global__ void k_fill(const int* __restrict__ src, const int* __restrict__ dst,
                       const float* __restrict__ xin, int e, int n) {
    int j = blockIdx.x * 256 + threadIdx.x;
    if (j < e) {
        int p = atomicAdd(&g_fill[dst[j]], 1);
        g_col[p] = src[j];
    }
    if (j < n * 32) {
        int row = j >> 5;
        int q   = j & 31;
        float4 v = *(const float4*)&xin[(size_t)row * HID + q * 4];
        float w = g_dinv[row];
        __half2 a = __floats2half2_rn(v.x * w, v.y * w);
        __half2 b = __floats2half2_rn(v.z * w, v.w * w);
        uint2 o = make_uint2(*(u32t*)&a, *(u32t*)&b);
        *(uint2*)&g_fh[(size_t)row * (HID / 2) + q * 2] = o;
    }
    if (j < n) g_deg[j] = 0;   // ready for next call (first call: static zero)
}

// ---------------- SpMM: fp16 gather, fp32 accumulate (round-10 proven) ----------------
__global__ void k_spmm(int n) {
    int row = blockIdx.x * 8 + (threadIdx.x >> 5);
    if (row >= n) return;
    int lane = threadIdx.x & 31;
    int e0 = g_rowptr[row];
    int e1 = g_rowptr[row + 1];
    int co = lane * 2;
    float4 acc0 = make_float4(0.f, 0.f, 0.f, 0.f);
    float4 acc1 = make_float4(0.f, 0.f, 0.f, 0.f);
    int e = e0;
    for (; e + 4 <= e1; e += 4) {
        int s0 = g_col[e];
        int s1 = g_col[e + 1];
        int s2 = g_col[e + 2];
        int s3 = g_col[e + 3];
        uint2 f0 = *(const uint2*)&g_fh[(size_t)s0 * (HID / 2) + co];
        uint2 f1 = *(const uint2*)&g_fh[(size_t)s1 * (HID / 2) + co];
        uint2 f2 = *(const uint2*)&g_fh[(size_t)s2 * (HID / 2) + co];
        uint2 f3 = *(const uint2*)&g_fh[(size_t)s3 * (HID / 2) + co];
        float2 a0 = __half22float2(*(__half2*)&f0.x), b0 = __half22float2(*(__half2*)&f0.y);
        float2 a1 = __half22float2(*(__half2*)&f1.x), b1 = __half22float2(*(__half2*)&f1.y);
        float2 a2 = __half22float2(*(__half2*)&f2.x), b2 = __half22float2(*(__half2*)&f2.y);
        float2 a3 = __half22float2(*(__half2*)&f3.x), b3 = __half22float2(*(__half2*)&f3.y);
        acc0.x += a0.x; acc0.y += a0.y; acc0.z += b0.x; acc0.w += b0.y;
        acc1.x += a1.x; acc1.y += a1.y; acc1.z += b1.x; acc1.w += b1.y;
        acc0.x += a2.x; acc0.y += a2.y; acc0.z += b2.x; acc0.w += b2.y;
        acc1.x += a3.x; acc1.y += a3.y; acc1.z += b3.x; acc1.w += b3.y;
    }
    for (; e < e1; e++) {
        int s = g_col[e];
        uint2 f = *(const uint2*)&g_fh[(size_t)s * (HID / 2) + co];
        float2 a = __half22float2(*(__half2*)&f.x), b = __half22float2(*(__half2*)&f.y);
        acc0.x += a.x; acc0.y += a.y; acc0.z += b.x; acc0.w += b.y;
    }
    float sc = -g_dinv[row];
    float4 o;
    o.x = (acc0.x + acc1.x) * sc;
    o.y = (acc0.y + acc1.y) * sc;
    o.z = (acc0.z + acc1.z) * sc;
    o.w = (acc0.w + acc1.w) * sc;
    *(float4*)&g_tx1[(size_t)row * HID + lane * 4] = o;
}

// ---------------- tensor GEMM, fp16 A + fp16 hi/lo W ----------------
// K blocks 0-3: A = g_fh direct uint2 copy (premultiplied by dinv); after kb 3
// the accumulator is rescaled by 1/dinv[row] (row-scaling commutes with @W).
// K blocks 4-7: A = g_tx1, converted fp32->fp16 on the fly.
// layer 0 epilogue: g_fh = half(relu(acc+b) * dinv)   (no fp32 h1 at all)
// layer 1 epilogue: g_h2 = relu(acc+b)                (for segmax)
__global__ __launch_bounds__(256, 2) void k_gemm_tc(int layer,
                                                    const float* __restrict__ bias,
                                                    int n) {
    const u32t* __restrict__ Whi = &g_Wfhi[layer * (HID * HID)];
    const u32t* __restrict__ Wlo = &g_Wflo[layer * (HID * HID)];

    __shared__ u32t As [2][GBM][8];
    __shared__ u32t WsH[2][HID][8];
    __shared__ u32t WsL[2][HID][8];

    int tid  = threadIdx.x;
    int lane = tid & 31;
    int wid  = tid >> 5;
    int wm   = wid & 1;
    int wn   = wid >> 1;
    int lr   = lane >> 2;
    int lc   = lane & 3;
    int bm   = blockIdx.x * GBM;
    int swl  = lr & 6;
    int ca   = lc ^ swl;

    float acc[4][4][4];
#pragma unroll
    for (int mi = 0; mi < 4; mi++)
#pragma unroll
        for (int ni = 0; ni < 4; ni++)
#pragma unroll
            for (int q = 0; q < 4; q++) acc[mi][ni][q] = 0.f;

    int tr = tid >> 2;
    int tq = tid & 3;

    for (int kb = 0; kb < 8; kb++) {
        int kg = kb * 32;
        bool direct = (kg < HID);      // X-part: read g_fh directly
        int kcol = kg & (HID - 1);

#pragma unroll
        for (int h = 0; h < 2; h++) {
#pragma unroll
            for (int p = 0; p < 2; p++) {
                int rl = tr + p * 64;
                int sw = rl & 6;
                int cc = (tq * 2) ^ sw;
                int row = bm + rl;
                uint2 av = make_uint2(0u, 0u);
                if (direct) {
                    if (row < n)
                        av = *(const uint2*)&g_fh[(size_t)row * 64 + (kcol >> 1) + h * 8 + tq * 2];
                } else {
                    float4 v = make_float4(0.f, 0.f, 0.f, 0.f);
                    if (row < n)
                        v = *(const float4*)&g_tx1[(size_t)row * HID + kcol + h * 16 + tq * 4];
                    __half2 p0 = __floats2half2_rn(v.x, v.y);
                    __half2 p1 = __floats2half2_rn(v.z, v.w);
                    av.x = *(u32t*)&p0;
                    av.y = *(u32t*)&p1;
                }
                *(uint2*)&As[h][rl][cc] = av;
                int wo = rl * 128 + (kg + h * 16) / 2 + tq * 2;
                *(uint2*)&WsH[h][rl][cc] = *(const uint2*)&Whi[wo];
                *(uint2*)&WsL[h][rl][cc] = *(const uint2*)&Wlo[wo];
            }
        }
        __syncthreads();

#pragma unroll
        for (int h = 0; h < 2; h++) {
            u32t bh[4][2], bl[4][2];
#pragma unroll
            for (int ni = 0; ni < 4; ni++) {
                int n0 = wn * 32 + ni * 8 + lr;
                bh[ni][0] = WsH[h][n0][ca];
                bh[ni][1] = WsH[h][n0][ca ^ 4];
                bl[ni][0] = WsL[h][n0][ca];
                bl[ni][1] = WsL[h][n0][ca ^ 4];
            }
#pragma unroll
            for (int mi = 0; mi < 4; mi++) {
                int m0 = wm * 64 + mi * 16;
                u32t a[4];
                a[0] = As[h][m0 + lr][ca];
                a[1] = As[h][m0 + lr + 8][ca];
                a[2] = As[h][m0 + lr][ca ^ 4];
                a[3] = As[h][m0 + lr + 8][ca ^ 4];
#pragma unroll
                for (int ni = 0; ni < 4; ni++) {
                    mma_f16(acc[mi][ni], a, bh[ni]);
                    mma_f16(acc[mi][ni], a, bl[ni]);
                }
            }
        }
        __syncthreads();

        if (kb == 3) {
            // end of X-part: undo the dinv premultiplication of g_fh rows
#pragma unroll
            for (int mi = 0; mi < 4; mi++) {
                int r0 = bm + wm * 64 + mi * 16 + lr;
                int r1 = r0 + 8;
                float s0 = (r0 < n) ? (1.0f / g_dinv[r0]) : 0.f;
                float s1 = (r1 < n) ? (1.0f / g_dinv[r1]) : 0.f;
#pragma unroll
                for (int ni = 0; ni < 4; ni++) {
                    acc[mi][ni][0] *= s0;
                    acc[mi][ni][1] *= s0;
                    acc[mi][ni][2] *= s1;
                    acc[mi][ni][3] *= s1;
                }
            }
        }
    }

    if (layer == 0) {
        // epilogue: g_fh = half(relu(acc+bias) * dinv); no fp32 h1
#pragma unroll
        for (int mi = 0; mi < 4; mi++) {
            int r0 = bm + wm * 64 + mi * 16 + lr;
            int r1 = r0 + 8;
            float w0 = (r0 < n) ? g_dinv[r0] : 0.f;
            float w1 = (r1 < n) ? g_dinv[r1] : 0.f;
#pragma unroll
            for (int ni = 0; ni < 4; ni++) {
                int col = wn * 32 + ni * 8 + lc * 2;
                float2 bv = *(const float2*)&bias[col];
                if (r0 < n) {
                    float v0 = fmaxf(acc[mi][ni][0] + bv.x, 0.f);
                    float v1 = fmaxf(acc[mi][ni][1] + bv.y, 0.f);
                    __half2 hh = __floats2half2_rn(v0 * w0, v1 * w0);
                    g_fh[(size_t)r0 * 64 + (col >> 1)] = *(u32t*)&hh;
                }
                if (r1 < n) {
                    float v2 = fmaxf(acc[mi][ni][2] + bv.x, 0.f);
                    float v3 = fmaxf(acc[mi][ni][3] + bv.y, 0.f);
                    __half2 hh = __floats2half2_rn(v2 * w1, v3 * w1);
                    g_fh[(size_t)r1 * 64 + (col >> 1)] = *(u32t*)&hh;
                }
            }
        }
    } else {
        // epilogue: g_h2 = relu(acc+bias) for segmax
#pragma unroll
        for (int mi = 0; mi < 4; mi++) {
            int r0 = bm + wm * 64 + mi * 16 + lr;
            int r1 = r0 + 8;
#pragma unroll
            for (int ni = 0; ni < 4; ni++) {
                int col = wn * 32 + ni * 8 + lc * 2;
                float2 bv = *(const float2*)&bias[col];
                if (r0 < n) {
                    float2 o;
                    o.x = fmaxf(acc[mi][ni][0] + bv.x, 0.f);
                    o.y = fmaxf(acc[mi][ni][1] + bv.y, 0.f);
                    *(float2*)&g_h2[(size_t)r0 * HID + col] = o;
                }
                if (r1 < n) {
                    float2 o;
                    o.x = fmaxf(acc[mi][ni][2] + bv.x, 0.f);
                    o.y = fmaxf(acc[mi][ni][3] + bv.y, 0.f);
                    *(float2*)&g_h2[(size_t)r1 * HID + col] = o;
                }
            }
        }
    }
}

// ---------------- segment max (round-10 proven) ----------------
__global__ void k_segmax(int gsize) {
    __shared__ float sm[8][HID];
    int g = blockIdx.x;
    int warp = threadIdx.x >> 5;
    int lane = threadIdx.x & 31;
    float4 m = make_float4(0.f, 0.f, 0.f, 0.f);
    int r0 = g * gsize;
    for (int r = r0 + warp; r < r0 + gsize; r += 8) {
        float4 v = *(const float4*)&g_h2[(size_t)r * HID + lane * 4];
        m.x = fmaxf(m.x, v.x);
        m.y = fmaxf(m.y, v.y);
        m.z = fmaxf(m.z, v.z);
        m.w = fmaxf(m.w, v.w);
    }
    *(float4*)&sm[warp][lane * 4] = m;
    __syncthreads();
    if (threadIdx.x < HID) {
        int f = threadIdx.x;
        float mm = sm[0][f];
#pragma unroll
        for (int w = 1; w < 8; w++) mm = fmaxf(mm, sm[w][f]);
        g_hg[g * HID + f] = mm;
    }
}

// ---------------- classifier head ----------------
__global__ void k_final(const float* __restrict__ Wc, const float* __restrict__ bc,
                        float* __restrict__ out, int nb) {
    int t = blockIdx.x * blockDim.x + threadIdx.x;
    if (t >= nb * 10) return;
    int g = t / 10;
    int c = t % 10;
    float acc = bc[c];
#pragma unroll 8
    for (int k = 0; k < HID; k++) acc += g_hg[g * HID + k] * Wc[k * 10 + c];
    out[t] = acc;
}

// ---------------- launch ----------------
extern "C" void kernel_launch(void* const* d_in, const int* in_sizes, int n_in,
                              void* d_out, int out_size) {
    const float* x   = (const float*)d_in[0];
    const float* W1  = (const float*)d_in[1];
    const float* b1  = (const float*)d_in[2];
    const float* W2  = (const float*)d_in[3];
    const float* b2  = (const float*)d_in[4];
    const float* Wc  = (const float*)d_in[5];
    const float* bc  = (const float*)d_in[6];
    const int*   src = (const int*)d_in[7];
    const int*   dst = (const int*)d_in[8];
    float* out = (float*)d_out;

    int e = in_sizes[7];
    int n = in_sizes[9];
    int nb_graphs = out_size / 10;
    int gsize = n / nb_graphs;
    int nbscan = (n + 1023) / 1024;
    int nGemm = (n + GBM - 1) / GBM;

    int histN = (e > 32768 ? e : 32768);
    int fillN = (e > n * 32 ? e : n * 32);

    k_hist<<<(histN + 255) / 256, 256>>>(dst, W1, W2, e);
    k_scanA<<<nbscan, 1024>>>(n);
    k_scanB<<<1, NB_SCAN>>>(nbscan);
    k_scanC<<<nbscan, 1024>>>(n, e);
    k_fill<<<(fillN + 255) / 256, 256>>>(src, dst, x, e, n);

    // layer 1
    k_spmm<<<(n + 7) / 8, 256>>>(n);
    k_gemm_tc<<<nGemm, 256>>>(0, b1, n);
    // layer 2
    k_spmm<<<(n + 7) / 8, 256>>>(n);
    k_gemm_tc<<<nGemm, 256>>>(1, b2, n);

    k_segmax<<<nb_graphs, 256>>>(gsize);
    k_final<<<1, 512>>>(Wc, bc, out, nb_graphs);
}

// round 15
// speedup vs baseline: 1.7615x; 1.1052x over previous
#include <cuda_runtime.h>
#include <cuda_fp16.h>
#include <cstdint>

#define N_NODES 100000
#define E_MAX   1600000
#define HID     128
#define NB_SCAN 128
#define GBM 128

typedef unsigned long long u64t;
typedef unsigned int u32t;

// ---------------- device scratch (no allocations allowed) ----------------
__device__ int   g_deg[N_NODES];
__device__ int   g_rowptr[N_NODES + 1];
__device__ int   g_fill[N_NODES];
__device__ int   g_bsum[NB_SCAN];
__device__ int   g_boff[NB_SCAN];
__device__ int   g_col[E_MAX];
__device__ float g_dinv[N_NODES];
__device__ u32t  g_hg [64 * HID];                      // float bits, atomicMax (relu>=0)
__device__ u32t  g_Wfhi[2 * HID * HID];                // fp16 pairs, W transposed [n][k/2]
__device__ u32t  g_Wflo[2 * HID * HID];
__device__ u32t  g_fh [(size_t)N_NODES * (HID / 2)];   // fp16 dinv-premultiplied features
__device__ u32t  g_txh[(size_t)N_NODES * (HID / 2)];   // fp16 Tx1 (raw, not premultiplied)

// ---------------- helpers ----------------
__device__ __forceinline__ void mma_f16(float* c, const u32t* a, const u32t* b) {
    asm volatile("mma.sync.aligned.m16n8k16.row.col.f32.f16.f16.f32 "
        "{%0,%1,%2,%3}, {%4,%5,%6,%7}, {%8,%9}, {%0,%1,%2,%3};"
        : "+f"(c[0]), "+f"(c[1]), "+f"(c[2]), "+f"(c[3])
        : "r"(a[0]), "r"(a[1]), "r"(a[2]), "r"(a[3]), "r"(b[0]), "r"(b[1]));
}

// ---------------- 1. hist + W prep (fp16 hi/lo) + zero g_hg ----------------
__global__ void k_hist(const int* __restrict__ dst,
                       const float* __restrict__ W1, const float* __restrict__ W2, int e) {
    int i = blockIdx.x * 256 + threadIdx.x;
    if (i < e) atomicAdd(&g_deg[dst[i]], 1);
    if (i < 32768) {
        int l  = i >> 14;
        int r  = i & 16383;
        int nn = r >> 7;
        int k2 = r & 127;
        const float* Wl = l ? W2 : W1;
        float v0 = Wl[(size_t)(2 * k2) * HID + nn];
        float v1 = Wl[(size_t)(2 * k2 + 1) * HID + nn];
        __half h0 = __float2half_rn(v0);
        __half h1 = __float2half_rn(v1);
        float l0 = v0 - __half2float(h0);
        float l1 = v1 - __half2float(h1);
        int o = l * (HID * HID) + nn * 128 + k2;
        __half2 HH = __halves2half2(h0, h1);
        __half2 LL = __floats2half2_rn(l0, l1);
        g_Wfhi[o] = *(u32t*)&HH;
        g_Wflo[o] = *(u32t*)&LL;
    }
    if (i < 64 * HID) g_hg[i] = 0u;
}

// ---------------- 2-4. scan (round-10/13 proven) ----------------
__global__ void k_scanA(int n) {
    __shared__ int s[1024];
    int tid = threadIdx.x;
    int i = blockIdx.x * 1024 + tid;
    int v = (i < n) ? g_deg[i] : 0;
    s[tid] = v;
    __syncthreads();
    for (int off = 1; off < 1024; off <<= 1) {
        int t = (tid >= off) ? s[tid - off] : 0;
        __syncthreads();
        s[tid] += t;
        __syncthreads();
    }
    if (i < n) g_rowptr[i] = s[tid] - v;
    if (tid == 1023) g_bsum[blockIdx.x] = s[1023];
}

__global__ void k_scanB(int nb) {
    __shared__ int s[NB_SCAN];
    int tid = threadIdx.x;
    int v = (tid < nb) ? g_bsum[tid] : 0;
    s[tid] = v;
    __syncthreads();
    for (int off = 1; off < NB_SCAN; off <<= 1) {
        int t = (tid >= off) ? s[tid - off] : 0;
        __syncthreads();
        s[tid] += t;
        __syncthreads();
    }
    s[tid] -= v;
    g_boff[tid] = s[tid];
}

__global__ void k_scanC(int n, int e) {
    int i = blockIdx.x * 1024 + threadIdx.x;
    if (i < n) {
        int rp = g_rowptr[i] + g_boff[i >> 10];
        g_rowptr[i] = rp;
        g_fill[i]   = rp;
        g_dinv[i]   = rsqrtf(fmaxf((float)g_deg[i], 1.0f));
        if (i == n - 1) g_rowptr[n] = e;
    }
}

// ---------------- 5. CSR fill + tohalf(x) + zero deg ----------------
__global__ void k_fill(const int* __restrict__ src, const int* __restrict__ dst,
                       const float* __restrict__ xin, int e, int n) {
    int j = blockIdx.x * 256 + threadIdx.x;
    if (j < e) {
        int p = atomicAdd(&g_fill[dst[j]], 1);
        g_col[p] = src[j];
    }
    if (j < n * 32) {
        int row = j >> 5;
        int q   = j & 31;
        float4 v = *(const float4*)&xin[(size_t)row * HID + q * 4];
        float w = g_dinv[row];
        __half2 a = __floats2half2_rn(v.x * w, v.y * w);
        __half2 b = __floats2half2_rn(v.z * w, v.w * w);
        uint2 o = make_uint2(*(u32t*)&a, *(u32t*)&b);
        *(uint2*)&g_fh[(size_t)row * (HID / 2) + q * 2] = o;
    }
    if (j < n) g_deg[j] = 0;   // ready for next call (first call: static zero)
}

// ---------------- SpMM: fp16 gather, fp32 accumulate, fp16 store ----------------
__global__ void k_spmm(int n) {
    int row = blockIdx.x * 8 + (threadIdx.x >> 5);
    if (row >= n) return;
    int lane = threadIdx.x & 31;
    int e0 = g_rowptr[row];
    int e1 = g_rowptr[row + 1];
    int co = lane * 2;
    float4 acc0 = make_float4(0.f, 0.f, 0.f, 0.f);
    float4 acc1 = make_float4(0.f, 0.f, 0.f, 0.f);
    int e = e0;
    for (; e + 4 <= e1; e += 4) {
        int s0 = g_col[e];
        int s1 = g_col[e + 1];
        int s2 = g_col[e + 2];
        int s3 = g_col[e + 3];
        uint2 f0 = *(const uint2*)&g_fh[(size_t)s0 * (HID / 2) + co];
        uint2 f1 = *(const uint2*)&g_fh[(size_t)s1 * (HID / 2) + co];
        uint2 f2 = *(const uint2*)&g_fh[(size_t)s2 * (HID / 2) + co];
        uint2 f3 = *(const uint2*)&g_fh[(size_t)s3 * (HID / 2) + co];
        float2 a0 = __half22float2(*(__half2*)&f0.x), b0 = __half22float2(*(__half2*)&f0.y);
        float2 a1 = __half22float2(*(__half2*)&f1.x), b1 = __half22float2(*(__half2*)&f1.y);
        float2 a2 = __half22float2(*(__half2*)&f2.x), b2 = __half22float2(*(__half2*)&f2.y);
        float2 a3 = __half22float2(*(__half2*)&f3.x), b3 = __half22float2(*(__half2*)&f3.y);
        acc0.x += a0.x; acc0.y += a0.y; acc0.z += b0.x; acc0.w += b0.y;
        acc1.x += a1.x; acc1.y += a1.y; acc1.z += b1.x; acc1.w += b1.y;
        acc0.x += a2.x; acc0.y += a2.y; acc0.z += b2.x; acc0.w += b2.y;
        acc1.x += a3.x; acc1.y += a3.y; acc1.z += b3.x; acc1.w += b3.y;
    }
    for (; e < e1; e++) {
        int s = g_col[e];
        uint2 f = *(const uint2*)&g_fh[(size_t)s * (HID / 2) + co];
        float2 a = __half22float2(*(__half2*)&f.x), b = __half22float2(*(__half2*)&f.y);
        acc0.x += a.x; acc0.y += a.y; acc0.z += b.x; acc0.w += b.y;
    }
    float sc = -g_dinv[row];
    __half2 h0 = __floats2half2_rn((acc0.x + acc1.x) * sc, (acc0.y + acc1.y) * sc);
    __half2 h1 = __floats2half2_rn((acc0.z + acc1.z) * sc, (acc0.w + acc1.w) * sc);
    uint2 o = make_uint2(*(u32t*)&h0, *(u32t*)&h1);
    *(uint2*)&g_txh[(size_t)row * (HID / 2) + co] = o;
}

// ---------------- tensor GEMM, all-fp16 A (direct uint2 loads) ----------------
// K blocks 0-3: A = g_fh (dinv-premultiplied); rescale acc by 1/dinv at kb==3.
// K blocks 4-7: A = g_txh (raw Tx1).
// layer 0 epilogue: g_fh = half(relu(acc+b) * dinv)
// layer 1 epilogue: fused segment max -> atomicMax into g_hg (no h2 buffer)
__global__ __launch_bounds__(256, 2) void k_gemm_tc(int layer,
                                                    const float* __restrict__ bias,
                                                    int n, int gsize, int nb) {
    const u32t* __restrict__ Whi = &g_Wfhi[layer * (HID * HID)];
    const u32t* __restrict__ Wlo = &g_Wflo[layer * (HID * HID)];

    __shared__ u32t As [2][GBM][8];
    __shared__ u32t WsH[2][HID][8];
    __shared__ u32t WsL[2][HID][8];
    __shared__ u32t red[256];

    int tid  = threadIdx.x;
    int lane = tid & 31;
    int wid  = tid >> 5;
    int wm   = wid & 1;
    int wn   = wid >> 1;
    int lr   = lane >> 2;
    int lc   = lane & 3;
    int bm   = blockIdx.x * GBM;
    int swl  = lr & 6;
    int ca   = lc ^ swl;

    float acc[4][4][4];
#pragma unroll
    for (int mi = 0; mi < 4; mi++)
#pragma unroll
        for (int ni = 0; ni < 4; ni++)
#pragma unroll
            for (int q = 0; q < 4; q++) acc[mi][ni][q] = 0.f;

    int tr = tid >> 2;
    int tq = tid & 3;

    for (int kb = 0; kb < 8; kb++) {
        int kg = kb * 32;
        const u32t* __restrict__ Abase = (kg < HID) ? g_fh : g_txh;
        int kcol = kg & (HID - 1);

#pragma unroll
        for (int h = 0; h < 2; h++) {
#pragma unroll
            for (int p = 0; p < 2; p++) {
                int rl = tr + p * 64;
                int sw = rl & 6;
                int cc = (tq * 2) ^ sw;
                int row = bm + rl;
                uint2 av = make_uint2(0u, 0u);
                if (row < n)
                    av = *(const uint2*)&Abase[(size_t)row * 64 + (kcol >> 1) + h * 8 + tq * 2];
                *(uint2*)&As[h][rl][cc] = av;
                int wo = rl * 128 + (kg + h * 16) / 2 + tq * 2;
                *(uint2*)&WsH[h][rl][cc] = *(const uint2*)&Whi[wo];
                *(uint2*)&WsL[h][rl][cc] = *(const uint2*)&Wlo[wo];
            }
        }
        __syncthreads();

#pragma unroll
        for (int h = 0; h < 2; h++) {
            u32t bh[4][2], bl[4][2];
#pragma unroll
            for (int ni = 0; ni < 4; ni++) {
                int n0 = wn * 32 + ni * 8 + lr;
                bh[ni][0] = WsH[h][n0][ca];
                bh[ni][1] = WsH[h][n0][ca ^ 4];
                bl[ni][0] = WsL[h][n0][ca];
                bl[ni][1] = WsL[h][n0][ca ^ 4];
            }
#pragma unroll
            for (int mi = 0; mi < 4; mi++) {
                int m0 = wm * 64 + mi * 16;
                u32t a[4];
                a[0] = As[h][m0 + lr][ca];
                a[1] = As[h][m0 + lr + 8][ca];
                a[2] = As[h][m0 + lr][ca ^ 4];
                a[3] = As[h][m0 + lr + 8][ca ^ 4];
#pragma unroll
                for (int ni = 0; ni < 4; ni++) {
                    mma_f16(acc[mi][ni], a, bh[ni]);
                    mma_f16(acc[mi][ni], a, bl[ni]);
                }
            }
        }
        __syncthreads();

        if (kb == 3) {
            // end of X-part: undo the dinv premultiplication of g_fh rows
#pragma unroll
            for (int mi = 0; mi < 4; mi++) {
                int r0 = bm + wm * 64 + mi * 16 + lr;
                int r1 = r0 + 8;
                float s0 = (r0 < n) ? (1.0f / g_dinv[r0]) : 0.f;
                float s1 = (r1 < n) ? (1.0f / g_dinv[r1]) : 0.f;
#pragma unroll
                for (int ni = 0; ni < 4; ni++) {
                    acc[mi][ni][0] *= s0;
                    acc[mi][ni][1] *= s0;
                    acc[mi][ni][2] *= s1;
                    acc[mi][ni][3] *= s1;
                }
            }
        }
    }

    if (layer == 0) {
        // epilogue: g_fh = half(relu(acc+bias) * dinv)
#pragma unroll
        for (int mi = 0; mi < 4; mi++) {
            int r0 = bm + wm * 64 + mi * 16 + lr;
            int r1 = r0 + 8;
            float w0 = (r0 < n) ? g_dinv[r0] : 0.f;
            float w1 = (r1 < n) ? g_dinv[r1] : 0.f;
#pragma unroll
            for (int ni = 0; ni < 4; ni++) {
                int col = wn * 32 + ni * 8 + lc * 2;
                float2 bv = *(const float2*)&bias[col];
                if (r0 < n) {
                    float v0 = fmaxf(acc[mi][ni][0] + bv.x, 0.f);
                    float v1 = fmaxf(acc[mi][ni][1] + bv.y, 0.f);
                    __half2 hh = __floats2half2_rn(v0 * w0, v1 * w0);
                    g_fh[(size_t)r0 * 64 + (col >> 1)] = *(u32t*)&hh;
                }
                if (r1 < n) {
                    float v2 = fmaxf(acc[mi][ni][2] + bv.x, 0.f);
                    float v3 = fmaxf(acc[mi][ni][3] + bv.y, 0.f);
                    __half2 hh = __floats2half2_rn(v2 * w1, v3 * w1);
                    g_fh[(size_t)r1 * 64 + (col >> 1)] = *(u32t*)&hh;
                }
            }
        }
    } else {
        // epilogue: fused segment max (block spans at most 2 graphs: GBM < gsize)
        if (tid < 256) red[tid] = 0u;
        __syncthreads();
        int g0  = bm / gsize;
        int bnd = (g0 + 1) * gsize;
#pragma unroll
        for (int mi = 0; mi < 4; mi++) {
            int r0 = bm + wm * 64 + mi * 16 + lr;
            int r1 = r0 + 8;
#pragma unroll
            for (int ni = 0; ni < 4; ni++) {
                int col = wn * 32 + ni * 8 + lc * 2;
                float2 bv = *(const float2*)&bias[col];
                if (r0 < n) {
                    float v0 = fmaxf(acc[mi][ni][0] + bv.x, 0.f);
                    float v1 = fmaxf(acc[mi][ni][1] + bv.y, 0.f);
                    int s = (r0 >= bnd) ? 128 : 0;
                    atomicMax(&red[s + col], __float_as_uint(v0));
                    atomicMax(&red[s + col + 1], __float_as_uint(v1));
                }
                if (r1 < n) {
                    float v2 = fmaxf(acc[mi][ni][2] + bv.x, 0.f);
                    float v3 = fmaxf(acc[mi][ni][3] + bv.y, 0.f);
                    int s = (r1 >= bnd) ? 128 : 0;
                    atomicMax(&red[s + col], __float_as_uint(v2));
                    atomicMax(&red[s + col + 1], __float_as_uint(v3));
                }
            }
        }
        __syncthreads();
        if (tid < 256) {
            int seg = tid >> 7;
            int c   = tid & 127;
            int g   = g0 + seg;
            bool has = (seg == 0) || (bnd < bm + GBM && bnd < n);
            if (g < nb && has) atomicMax(&g_hg[g * HID + c], red[tid]);
        }
    }
}

// ---------------- classifier head ----------------
__global__ void k_final(const float* __restrict__ Wc, const float* __restrict__ bc,
                        float* __restrict__ out, int nb) {
    int t = blockIdx.x * blockDim.x + threadIdx.x;
    if (t >= nb * 10) return;
    int g = t / 10;
    int c = t % 10;
    float acc = bc[c];
#pragma unroll 8
    for (int k = 0; k < HID; k++)
        acc += __uint_as_float(g_hg[g * HID + k]) * Wc[k * 10 + c];
    out[t] = acc;
}

// ---------------- launch ----------------
extern "C" void kernel_launch(void* const* d_in, const int* in_sizes, int n_in,
                              void* d_out, int out_size) {
    const float* x   = (const float*)d_in[0];
    const float* W1  = (const float*)d_in[1];
    const float* b1  = (const float*)d_in[2];
    const float* W2  = (const float*)d_in[3];
    const float* b2  = (const float*)d_in[4];
    const float* Wc  = (const float*)d_in[5];
    const float* bc  = (const float*)d_in[6];
    const int*   src = (const int*)d_in[7];
    const int*   dst = (const int*)d_in[8];
    float* out = (float*)d_out;

    int e = in_sizes[7];
    int n = in_sizes[9];
    int nb_graphs = out_size / 10;
    int gsize = n / nb_graphs;
    int nbscan = (n + 1023) / 1024;
    int nGemm = (n + GBM - 1) / GBM;

    int histN = (e > 32768 ? e : 32768);
    int fillN = (e > n * 32 ? e : n * 32);

    k_hist<<<(histN + 255) / 256, 256>>>(dst, W1, W2, e);
    k_scanA<<<nbscan, 1024>>>(n);
    k_scanB<<<1, NB_SCAN>>>(nbscan);
    k_scanC<<<nbscan, 1024>>>(n, e);
    k_fill<<<(fillN + 255) / 256, 256>>>(src, dst, x, e, n);

    // layer 1
    k_spmm<<<(n + 7) / 8, 256>>>(n);
    k_gemm_tc<<<nGemm, 256>>>(0, b1, n, gsize, nb_graphs);
    // layer 2
    k_spmm<<<(n + 7) / 8, 256>>>(n);
    k_gemm_tc<<<nGemm, 256>>>(1, b2, n, gsize, nb_graphs);

    k_final<<<1, 512>>>(Wc, bc, out, nb_graphs);
}

// round 16
// speedup vs baseline: 2.1040x; 1.1945x over previous
#include <cuda_runtime.h>
#include <cuda_fp16.h>
#include <cstdint>

#define N_NODES 100000
#define E_MAX   1600000
#define HID     128
#define NB_SCAN 128
#define GBM 128

typedef unsigned long long u64t;
typedef unsigned int u32t;

// ---------------- device scratch (no allocations allowed) ----------------
__device__ int   g_deg[N_NODES];
__device__ int   g_rowptr[N_NODES + 1];
__device__ int   g_fill[N_NODES];
__device__ int   g_bsum[NB_SCAN];
__device__ int   g_col[E_MAX];
__device__ float g_dinv[N_NODES];
__device__ u32t  g_hg [64 * HID];                      // float bits, atomicMax (relu>=0)
__device__ u32t  g_Wfh[2 * HID * HID];                 // fp16 pairs, W transposed [n][k/2]
__device__ u32t  g_fh [(size_t)N_NODES * (HID / 2)];   // fp16 dinv-premultiplied features
__device__ u32t  g_txh[(size_t)N_NODES * (HID / 2)];   // fp16 Tx1 (raw)

// ---------------- helpers ----------------
__device__ __forceinline__ void mma_f16(float* c, const u32t* a, const u32t* b) {
    asm volatile("mma.sync.aligned.m16n8k16.row.col.f32.f16.f16.f32 "
        "{%0,%1,%2,%3}, {%4,%5,%6,%7}, {%8,%9}, {%0,%1,%2,%3};"
        : "+f"(c[0]), "+f"(c[1]), "+f"(c[2]), "+f"(c[3])
        : "r"(a[0]), "r"(a[1]), "r"(a[2]), "r"(a[3]), "r"(b[0]), "r"(b[1]));
}

// ---------------- 1. hist + W prep (fp16) + zero g_hg ----------------
__global__ void k_hist(const int* __restrict__ dst,
                       const float* __restrict__ W1, const float* __restrict__ W2, int e) {
    int i = blockIdx.x * 256 + threadIdx.x;
    if (i < e) atomicAdd(&g_deg[dst[i]], 1);
    if (i < 32768) {
        int l  = i >> 14;
        int r  = i & 16383;
        int nn = r >> 7;
        int k2 = r & 127;
        const float* Wl = l ? W2 : W1;
        float v0 = Wl[(size_t)(2 * k2) * HID + nn];
        float v1 = Wl[(size_t)(2 * k2 + 1) * HID + nn];
        __half2 HH = __floats2half2_rn(v0, v1);
        g_Wfh[l * (HID * HID) + nn * 128 + k2] = *(u32t*)&HH;
    }
    if (i < 64 * HID) g_hg[i] = 0u;
}

// ---------------- 2. scanA (round-10/13 proven) ----------------
__global__ void k_scanA(int n) {
    __shared__ int s[1024];
    int tid = threadIdx.x;
    int i = blockIdx.x * 1024 + tid;
    int v = (i < n) ? g_deg[i] : 0;
    s[tid] = v;
    __syncthreads();
    for (int off = 1; off < 1024; off <<= 1) {
        int t = (tid >= off) ? s[tid - off] : 0;
        __syncthreads();
        s[tid] += t;
        __syncthreads();
    }
    if (i < n) g_rowptr[i] = s[tid] - v;
    if (tid == 1023) g_bsum[blockIdx.x] = s[1023];
}

// ---------------- 3. scanC with inline block-offset reduction (absorbs scanB) ----------------
__global__ void k_scanC(int n, int e, int nbscan) {
    __shared__ int sacc[32];
    __shared__ int sprefix;
    int tid = threadIdx.x;
    // sum of g_bsum[0 .. blockIdx.x-1]
    int v = (tid < blockIdx.x && tid < nbscan) ? g_bsum[tid] : 0;
#pragma unroll
    for (int o = 16; o > 0; o >>= 1) v += __shfl_down_sync(0xffffffffu, v, o);
    if ((tid & 31) == 0) sacc[tid >> 5] = v;
    __syncthreads();
    if (tid < 32) {
        int w = (tid < ((blockDim.x + 31) >> 5)) ? sacc[tid] : 0;
#pragma unroll
        for (int o = 16; o > 0; o >>= 1) w += __shfl_down_sync(0xffffffffu, w, o);
        if (tid == 0) sprefix = w;
    }
    __syncthreads();
    int boff = sprefix;

    int i = blockIdx.x * 1024 + tid;
    if (i < n) {
        int rp = g_rowptr[i] + boff;
        g_rowptr[i] = rp;
        g_fill[i]   = rp;
        g_dinv[i]   = rsqrtf(fmaxf((float)g_deg[i], 1.0f));
        if (i == n - 1) g_rowptr[n] = e;
    }
}

// ---------------- 4. CSR fill + tohalf(x) + zero deg ----------------
__global__ void k_fill(const int* __restrict__ src, const int* __restrict__ dst,
                       const float* __restrict__ xin, int e, int n) {
    int j = blockIdx.x * 256 + threadIdx.x;
    if (j < e) {
        int p = atomicAdd(&g_fill[dst[j]], 1);
        g_col[p] = src[j];
    }
    if (j < n * 32) {
        int row = j >> 5;
        int q   = j & 31;
        float4 v = *(const float4*)&xin[(size_t)row * HID + q * 4];
        float w = g_dinv[row];
        __half2 a = __floats2half2_rn(v.x * w, v.y * w);
        __half2 b = __floats2half2_rn(v.z * w, v.w * w);
        uint2 o = make_uint2(*(u32t*)&a, *(u32t*)&b);
        *(uint2*)&g_fh[(size_t)row * (HID / 2) + q * 2] = o;
    }
    if (j < n) g_deg[j] = 0;   // ready for next call (first call: static zero)
}

// ---------------- SpMM: fp16 gather, fp32 accumulate, fp16 store (R15 proven) ----------------
__global__ void k_spmm(int n) {
    int row = blockIdx.x * 8 + (threadIdx.x >> 5);
    if (row >= n) return;
    int lane = threadIdx.x & 31;
    int e0 = g_rowptr[row];
    int e1 = g_rowptr[row + 1];
    int co = lane * 2;
    float4 acc0 = make_float4(0.f, 0.f, 0.f, 0.f);
    float4 acc1 = make_float4(0.f, 0.f, 0.f, 0.f);
    int e = e0;
    for (; e + 4 <= e1; e += 4) {
        int s0 = g_col[e];
        int s1 = g_col[e + 1];
        int s2 = g_col[e + 2];
        int s3 = g_col[e + 3];
        uint2 f0 = *(const uint2*)&g_fh[(size_t)s0 * (HID / 2) + co];
        uint2 f1 = *(const uint2*)&g_fh[(size_t)s1 * (HID / 2) + co];
        uint2 f2 = *(const uint2*)&g_fh[(size_t)s2 * (HID / 2) + co];
        uint2 f3 = *(const uint2*)&g_fh[(size_t)s3 * (HID / 2) + co];
        float2 a0 = __half22float2(*(__half2*)&f0.x), b0 = __half22float2(*(__half2*)&f0.y);
        float2 a1 = __half22float2(*(__half2*)&f1.x), b1 = __half22float2(*(__half2*)&f1.y);
        float2 a2 = __half22float2(*(__half2*)&f2.x), b2 = __half22float2(*(__half2*)&f2.y);
        float2 a3 = __half22float2(*(__half2*)&f3.x), b3 = __half22float2(*(__half2*)&f3.y);
        acc0.x += a0.x; acc0.y += a0.y; acc0.z += b0.x; acc0.w += b0.y;
        acc1.x += a1.x; acc1.y += a1.y; acc1.z += b1.x; acc1.w += b1.y;
        acc0.x += a2.x; acc0.y += a2.y; acc0.z += b2.x; acc0.w += b2.y;
        acc1.x += a3.x; acc1.y += a3.y; acc1.z += b3.x; acc1.w += b3.y;
    }
    for (; e < e1; e++) {
        int s = g_col[e];
        uint2 f = *(const uint2*)&g_fh[(size_t)s * (HID / 2) + co];
        float2 a = __half22float2(*(__half2*)&f.x), b = __half22float2(*(__half2*)&f.y);
        acc0.x += a.x; acc0.y += a.y; acc0.z += b.x; acc0.w += b.y;
    }
    float sc = -g_dinv[row];
    __half2 h0 = __floats2half2_rn((acc0.x + acc1.x) * sc, (acc0.y + acc1.y) * sc);
    __half2 h1 = __floats2half2_rn((acc0.z + acc1.z) * sc, (acc0.w + acc1.w) * sc);
    uint2 o = make_uint2(*(u32t*)&h0, *(u32t*)&h1);
    *(uint2*)&g_txh[(size_t)row * (HID / 2) + co] = o;
}

// ---------------- tensor GEMM, fp16 A + fp16 W (single mma per k16) ----------------
// K blocks 0-3: A = g_fh (dinv-premultiplied); rescale acc by 1/dinv at kb==3.
// K blocks 4-7: A = g_txh.
// layer 0 epilogue: g_fh = half(relu(acc+b) * dinv)
// layer 1 epilogue: fused segment max -> atomicMax into g_hg
__global__ __launch_bounds__(256, 2) void k_gemm_tc(int layer,
                                                    const float* __restrict__ bias,
                                                    int n, int gsize, int nb) {
    const u32t* __restrict__ Wf = &g_Wfh[layer * (HID * HID)];

    __shared__ u32t As[2][GBM][8];
    __shared__ u32t Ws[2][HID][8];
    __shared__ u32t red[256];

    int tid  = threadIdx.x;
    int lane = tid & 31;
    int wid  = tid >> 5;
    int wm   = wid & 1;
    int wn   = wid >> 1;
    int lr   = lane >> 2;
    int lc   = lane & 3;
    int bm   = blockIdx.x * GBM;
    int swl  = lr & 6;
    int ca   = lc ^ swl;

    float acc[4][4][4];
#pragma unroll
    for (int mi = 0; mi < 4; mi++)
#pragma unroll
        for (int ni = 0; ni < 4; ni++)
#pragma unroll
            for (int q = 0; q < 4; q++) acc[mi][ni][q] = 0.f;

    int tr = tid >> 2;
    int tq = tid & 3;

    for (int kb = 0; kb < 8; kb++) {
        int kg = kb * 32;
        const u32t* __restrict__ Abase = (kg < HID) ? g_fh : g_txh;
        int kcol = kg & (HID - 1);

#pragma unroll
        for (int h = 0; h < 2; h++) {
#pragma unroll
            for (int p = 0; p < 2; p++) {
                int rl = tr + p * 64;
                int sw = rl & 6;
                int cc = (tq * 2) ^ sw;
                int row = bm + rl;
                uint2 av = make_uint2(0u, 0u);
                if (row < n)
                    av = *(const uint2*)&Abase[(size_t)row * 64 + (kcol >> 1) + h * 8 + tq * 2];
                *(uint2*)&As[h][rl][cc] = av;
                int wo = rl * 128 + (kg + h * 16) / 2 + tq * 2;
                *(uint2*)&Ws[h][rl][cc] = *(const uint2*)&Wf[wo];
            }
        }
        __syncthreads();

#pragma unroll
        for (int h = 0; h < 2; h++) {
            u32t bh[4][2];
#pragma unroll
            for (int ni = 0; ni < 4; ni++) {
                int n0 = wn * 32 + ni * 8 + lr;
                bh[ni][0] = Ws[h][n0][ca];
                bh[ni][1] = Ws[h][n0][ca ^ 4];
            }
#pragma unroll
            for (int mi = 0; mi < 4; mi++) {
                int m0 = wm * 64 + mi * 16;
                u32t a[4];
                a[0] = As[h][m0 + lr][ca];
                a[1] = As[h][m0 + lr + 8][ca];
                a[2] = As[h][m0 + lr][ca ^ 4];
                a[3] = As[h][m0 + lr + 8][ca ^ 4];
#pragma unroll
                for (int ni = 0; ni < 4; ni++) {
                    mma_f16(acc[mi][ni], a, bh[ni]);
                }
            }
        }
        __syncthreads();

        if (kb == 3) {
            // end of X-part: undo the dinv premultiplication of g_fh rows
#pragma unroll
            for (int mi = 0; mi < 4; mi++) {
                int r0 = bm + wm * 64 + mi * 16 + lr;
                int r1 = r0 + 8;
                float s0 = (r0 < n) ? (1.0f / g_dinv[r0]) : 0.f;
                float s1 = (r1 < n) ? (1.0f / g_dinv[r1]) : 0.f;
#pragma unroll
                for (int ni = 0; ni < 4; ni++) {
                    acc[mi][ni][0] *= s0;
                    acc[mi][ni][1] *= s0;
                    acc[mi][ni][2] *= s1;
                    acc[mi][ni][3] *= s1;
                }
            }
        }
    }

    if (layer == 0) {
        // epilogue: g_fh = half(relu(acc+bias) * dinv)
#pragma unroll
        for (int mi = 0; mi < 4; mi++) {
            int r0 = bm + wm * 64 + mi * 16 + lr;
            int r1 = r0 + 8;
            float w0 = (r0 < n) ? g_dinv[r0] : 0.f;
            float w1 = (r1 < n) ? g_dinv[r1] : 0.f;
#pragma unroll
            for (int ni = 0; ni < 4; ni++) {
                int col = wn * 32 + ni * 8 + lc * 2;
                float2 bv = *(const float2*)&bias[col];
                if (r0 < n) {
                    float v0 = fmaxf(acc[mi][ni][0] + bv.x, 0.f);
                    float v1 = fmaxf(acc[mi][ni][1] + bv.y, 0.f);
                    __half2 hh = __floats2half2_rn(v0 * w0, v1 * w0);
                    g_fh[(size_t)r0 * 64 + (col >> 1)] = *(u32t*)&hh;
                }
                if (r1 < n) {
                    float v2 = fmaxf(acc[mi][ni][2] + bv.x, 0.f);
                    float v3 = fmaxf(acc[mi][ni][3] + bv.y, 0.f);
                    __half2 hh = __floats2half2_rn(v2 * w1, v3 * w1);
                    g_fh[(size_t)r1 * 64 + (col >> 1)] = *(u32t*)&hh;
                }
            }
        }
    } else {
        // epilogue: fused segment max (block spans at most 2 graphs: GBM < gsize)
        if (tid < 256) red[tid] = 0u;
        __syncthreads();
        int g0  = bm / gsize;
        int bnd = (g0 + 1) * gsize;
#pragma unroll
        for (int mi = 0; mi < 4; mi++) {
            int r0 = bm + wm * 64 + mi * 16 + lr;
            int r1 = r0 + 8;
#pragma unroll
            for (int ni = 0; ni < 4; ni++) {
                int col = wn * 32 + ni * 8 + lc * 2;
                float2 bv = *(const float2*)&bias[col];
                if (r0 < n) {
                    float v0 = fmaxf(acc[mi][ni][0] + bv.x, 0.f);
                    float v1 = fmaxf(acc[mi][ni][1] + bv.y, 0.f);
                    int s = (r0 >= bnd) ? 128 : 0;
                    atomicMax(&red[s + col], __float_as_uint(v0));
                    atomicMax(&red[s + col + 1], __float_as_uint(v1));
                }
                if (r1 < n) {
                    float v2 = fmaxf(acc[mi][ni][2] + bv.x, 0.f);
                    float v3 = fmaxf(acc[mi][ni][3] + bv.y, 0.f);
                    int s = (r1 >= bnd) ? 128 : 0;
                    atomicMax(&red[s + col], __float_as_uint(v2));
                    atomicMax(&red[s + col + 1], __float_as_uint(v3));
                }
            }
        }
        __syncthreads();
        if (tid < 256) {
            int seg = tid >> 7;
            int c   = tid & 127;
            int g   = g0 + seg;
            bool has = (seg == 0) || (bnd < bm + GBM && bnd < n);
            if (g < nb && has) atomicMax(&g_hg[g * HID + c], red[tid]);
        }
    }
}

// ---------------- classifier head ----------------
__global__ void k_final(const float* __restrict__ Wc, const float* __restrict__ bc,
                        float* __restrict__ out, int nb) {
    int t = blockIdx.x * blockDim.x + threadIdx.x;
    if (t >= nb * 10) return;
    int g = t / 10;
    int c = t % 10;
    float acc = bc[c];
#pragma unroll 8
    for (int k = 0; k < HID; k++)
        acc += __uint_as_float(g_hg[g * HID + k]) * Wc[k * 10 + c];
    out[t] = acc;
}

// ---------------- launch ----------------
extern "C" void kernel_launch(void* const* d_in, const int* in_sizes, int n_in,
                              void* d_out, int out_size) {
    const float* x   = (const float*)d_in[0];
    const float* W1  = (const float*)d_in[1];
    const float* b1  = (const float*)d_in[2];
    const float* W2  = (const float*)d_in[3];
    const float* b2  = (const float*)d_in[4];
    const float* Wc  = (const float*)d_in[5];
    const float* bc  = (const float*)d_in[6];
    const int*   src = (const int*)d_in[7];
    const int*   dst = (const int*)d_in[8];
    float* out = (float*)d_out;

    int e = in_sizes[7];
    int n = in_sizes[9];
    int nb_graphs = out_size / 10;
    int gsize = n / nb_graphs;
    int nbscan = (n + 1023) / 1024;
    int nGemm = (n + GBM - 1) / GBM;

    int histN = (e > 32768 ? e : 32768);
    int fillN = (e > n * 32 ? e : n * 32);

    k_hist<<<(histN + 255) / 256, 256>>>(dst, W1, W2, e);
    k_scanA<<<nbscan, 1024>>>(n);
    k_scanC<<<nbscan, 1024>>>(n, e, nbscan);
    k_fill<<<(fillN + 255) / 256, 256>>>(src, dst, x, e, n);

    // layer 1
    k_spmm<<<(n + 7) / 8, 256>>>(n);
    k_gemm_tc<<<nGemm, 256>>>(0, b1, n, gsize, nb_graphs);
    // layer 2
    k_spmm<<<(n + 7) / 8, 256>>>(n);
    k_gemm_tc<<<nGemm, 256>>>(1, b2, n, gsize, nb_graphs);

    k_final<<<1, 512>>>(Wc, bc, out, nb_graphs);
}

// round 17
// speedup vs baseline: 2.1462x; 1.0201x over previous
#include <cuda_runtime.h>
#include <cuda_fp16.h>
#include <cstdint>

#define N_NODES 100000
#define E_MAX   1600000
#define HID     128
#define NB_SCAN 128
#define GBM 128

typedef unsigned long long u64t;
typedef unsigned int u32t;

// ---------------- device scratch (no allocations allowed) ----------------
__device__ int   g_deg[N_NODES];
__device__ int   g_rowptr[N_NODES + 1];
__device__ int   g_fill[N_NODES];
__device__ int   g_bsum[NB_SCAN];
__device__ int   g_col[E_MAX];
__device__ float g_dinv[N_NODES];
__device__ u32t  g_hg [64 * HID];                      // float bits, atomicMax (relu>=0)
__device__ u32t  g_Wfh[2 * HID * HID];                 // fp16 pairs, W transposed [n][k/2]
__device__ u32t  g_fh [(size_t)N_NODES * (HID / 2)];   // fp16 dinv-premultiplied features
__device__ u32t  g_txh[(size_t)N_NODES * (HID / 2)];   // fp16 Tx1 (raw)

// ---------------- helpers ----------------
__device__ __forceinline__ void mma_f16(float* c, const u32t* a, const u32t* b) {
    asm volatile("mma.sync.aligned.m16n8k16.row.col.f32.f16.f16.f32 "
        "{%0,%1,%2,%3}, {%4,%5,%6,%7}, {%8,%9}, {%0,%1,%2,%3};"
        : "+f"(c[0]), "+f"(c[1]), "+f"(c[2]), "+f"(c[3])
        : "r"(a[0]), "r"(a[1]), "r"(a[2]), "r"(a[3]), "r"(b[0]), "r"(b[1]));
}
__device__ __forceinline__ void fadd2(u64t &d, u64t a) {
    asm("add.rn.f32x2 %0, %0, %1;" : "+l"(d) : "l"(a));
}
__device__ __forceinline__ float2 unpack2(u64t v) {
    float2 f; asm("mov.b64 {%0, %1}, %2;" : "=f"(f.x), "=f"(f.y) : "l"(v)); return f;
}

// ---------------- 1. hist + W prep (fp16) + zero g_hg ----------------
__global__ void k_hist(const int* __restrict__ dst,
                       const float* __restrict__ W1, const float* __restrict__ W2, int e) {
    int i = blockIdx.x * 256 + threadIdx.x;
    if (i < e) atomicAdd(&g_deg[dst[i]], 1);
    if (i < 32768) {
        int l  = i >> 14;
        int r  = i & 16383;
        int nn = r >> 7;
        int k2 = r & 127;
        const float* Wl = l ? W2 : W1;
        float v0 = Wl[(size_t)(2 * k2) * HID + nn];
        float v1 = Wl[(size_t)(2 * k2 + 1) * HID + nn];
        __half2 HH = __floats2half2_rn(v0, v1);
        g_Wfh[l * (HID * HID) + nn * 128 + k2] = *(u32t*)&HH;
    }
    if (i < 64 * HID) g_hg[i] = 0u;
}

// ---------------- 2. scanA (round-10/13 proven) ----------------
__global__ void k_scanA(int n) {
    __shared__ int s[1024];
    int tid = threadIdx.x;
    int i = blockIdx.x * 1024 + tid;
    int v = (i < n) ? g_deg[i] : 0;
    s[tid] = v;
    __syncthreads();
    for (int off = 1; off < 1024; off <<= 1) {
        int t = (tid >= off) ? s[tid - off] : 0;
        __syncthreads();
        s[tid] += t;
        __syncthreads();
    }
    if (i < n) g_rowptr[i] = s[tid] - v;
    if (tid == 1023) g_bsum[blockIdx.x] = s[1023];
}

// ---------------- 3. scanC with inline block-offset reduction (R16 proven) ----------------
__global__ void k_scanC(int n, int e, int nbscan) {
    __shared__ int sacc[32];
    __shared__ int sprefix;
    int tid = threadIdx.x;
    int v = (tid < blockIdx.x && tid < nbscan) ? g_bsum[tid] : 0;
#pragma unroll
    for (int o = 16; o > 0; o >>= 1) v += __shfl_down_sync(0xffffffffu, v, o);
    if ((tid & 31) == 0) sacc[tid >> 5] = v;
    __syncthreads();
    if (tid < 32) {
        int w = (tid < ((blockDim.x + 31) >> 5)) ? sacc[tid] : 0;
#pragma unroll
        for (int o = 16; o > 0; o >>= 1) w += __shfl_down_sync(0xffffffffu, w, o);
        if (tid == 0) sprefix = w;
    }
    __syncthreads();
    int boff = sprefix;

    int i = blockIdx.x * 1024 + tid;
    if (i < n) {
        int rp = g_rowptr[i] + boff;
        g_rowptr[i] = rp;
        g_fill[i]   = rp;
        g_dinv[i]   = rsqrtf(fmaxf((float)g_deg[i], 1.0f));
        if (i == n - 1) g_rowptr[n] = e;
    }
}

// ---------------- 4. CSR fill + tohalf(x) + zero deg ----------------
__global__ void k_fill(const int* __restrict__ src, const int* __restrict__ dst,
                       const float* __restrict__ xin, int e, int n) {
    int j = blockIdx.x * 256 + threadIdx.x;
    if (j < e) {
        int p = atomicAdd(&g_fill[dst[j]], 1);
        g_col[p] = src[j];
    }
    if (j < n * 32) {
        int row = j >> 5;
        int q   = j & 31;
        float4 v = *(const float4*)&xin[(size_t)row * HID + q * 4];
        float w = g_dinv[row];
        __half2 a = __floats2half2_rn(v.x * w, v.y * w);
        __half2 b = __floats2half2_rn(v.z * w, v.w * w);
        uint2 o = make_uint2(*(u32t*)&a, *(u32t*)&b);
        *(uint2*)&g_fh[(size_t)row * (HID / 2) + q * 2] = o;
    }
    if (j < n) g_deg[j] = 0;   // ready for next call (first call: static zero)
}

// ---------------- SpMM: fp16 gather, fp16 pair-add, f32x2 accumulate ----------------
__global__ void k_spmm(int n) {
    int row = blockIdx.x * 8 + (threadIdx.x >> 5);
    if (row >= n) return;
    int lane = threadIdx.x & 31;
    int e0 = g_rowptr[row];
    int e1 = g_rowptr[row + 1];
    int co = lane * 2;
    u64t accA = 0ull, accB = 0ull;   // pair (0,1): cols 0-1, 2-3
    u64t accC = 0ull, accD = 0ull;   // pair (2,3)
    int e = e0;
    for (; e + 4 <= e1; e += 4) {
        int s0 = g_col[e];
        int s1 = g_col[e + 1];
        int s2 = g_col[e + 2];
        int s3 = g_col[e + 3];
        uint2 f0 = *(const uint2*)&g_fh[(size_t)s0 * (HID / 2) + co];
        uint2 f1 = *(const uint2*)&g_fh[(size_t)s1 * (HID / 2) + co];
        uint2 f2 = *(const uint2*)&g_fh[(size_t)s2 * (HID / 2) + co];
        uint2 f3 = *(const uint2*)&g_fh[(size_t)s3 * (HID / 2) + co];
        // one fp16 rounding level: add edge pairs
        __half2 p0 = __hadd2(*(__half2*)&f0.x, *(__half2*)&f1.x);
        __half2 p1 = __hadd2(*(__half2*)&f0.y, *(__half2*)&f1.y);
        __half2 p2 = __hadd2(*(__half2*)&f2.x, *(__half2*)&f3.x);
        __half2 p3 = __hadd2(*(__half2*)&f2.y, *(__half2*)&f3.y);
        float2 q0 = __half22float2(p0);
        float2 q1 = __half22float2(p1);
        float2 q2 = __half22float2(p2);
        float2 q3 = __half22float2(p3);
        fadd2(accA, *(u64t*)&q0);
        fadd2(accB, *(u64t*)&q1);
        fadd2(accC, *(u64t*)&q2);
        fadd2(accD, *(u64t*)&q3);
    }
    for (; e < e1; e++) {
        int s = g_col[e];
        uint2 f = *(const uint2*)&g_fh[(size_t)s * (HID / 2) + co];
        float2 a = __half22float2(*(__half2*)&f.x);
        float2 b = __half22float2(*(__half2*)&f.y);
        fadd2(accA, *(u64t*)&a);
        fadd2(accB, *(u64t*)&b);
    }
    fadd2(accA, accC);
    fadd2(accB, accD);
    float sc = -g_dinv[row];
    float2 ra = unpack2(accA);
    float2 rb = unpack2(accB);
    __half2 h0 = __floats2half2_rn(ra.x * sc, ra.y * sc);
    __half2 h1 = __floats2half2_rn(rb.x * sc, rb.y * sc);
    uint2 o = make_uint2(*(u32t*)&h0, *(u32t*)&h1);
    *(uint2*)&g_txh[(size_t)row * (HID / 2) + co] = o;
}

// ---------------- tensor GEMM, fp16 A + fp16 W (R16 proven) ----------------
__global__ __launch_bounds__(256, 2) void k_gemm_tc(int layer,
                                                    const float* __restrict__ bias,
                                                    int n, int gsize, int nb) {
    const u32t* __restrict__ Wf = &g_Wfh[layer * (HID * HID)];

    __shared__ u32t As[2][GBM][8];
    __shared__ u32t Ws[2][HID][8];
    __shared__ u32t red[256];

    int tid  = threadIdx.x;
    int lane = tid & 31;
    int wid  = tid >> 5;
    int wm   = wid & 1;
    int wn   = wid >> 1;
    int lr   = lane >> 2;
    int lc   = lane & 3;
    int bm   = blockIdx.x * GBM;
    int swl  = lr & 6;
    int ca   = lc ^ swl;

    float acc[4][4][4];
#pragma unroll
    for (int mi = 0; mi < 4; mi++)
#pragma unroll
        for (int ni = 0; ni < 4; ni++)
#pragma unroll
            for (int q = 0; q < 4; q++) acc[mi][ni][q] = 0.f;

    int tr = tid >> 2;
    int tq = tid & 3;

    for (int kb = 0; kb < 8; kb++) {
        int kg = kb * 32;
        const u32t* __restrict__ Abase = (kg < HID) ? g_fh : g_txh;
        int kcol = kg & (HID - 1);

#pragma unroll
        for (int h = 0; h < 2; h++) {
#pragma unroll
            for (int p = 0; p < 2; p++) {
                int rl = tr + p * 64;
                int sw = rl & 6;
                int cc = (tq * 2) ^ sw;
                int row = bm + rl;
                uint2 av = make_uint2(0u, 0u);
                if (row < n)
                    av = *(const uint2*)&Abase[(size_t)row * 64 + (kcol >> 1) + h * 8 + tq * 2];
                *(uint2*)&As[h][rl][cc] = av;
                int wo = rl * 128 + (kg + h * 16) / 2 + tq * 2;
                *(uint2*)&Ws[h][rl][cc] = *(const uint2*)&Wf[wo];
            }
        }
        __syncthreads();

#pragma unroll
        for (int h = 0; h < 2; h++) {
            u32t bh[4][2];
#pragma unroll
            for (int ni = 0; ni < 4; ni++) {
                int n0 = wn * 32 + ni * 8 + lr;
                bh[ni][0] = Ws[h][n0][ca];
                bh[ni][1] = Ws[h][n0][ca ^ 4];
            }
#pragma unroll
            for (int mi = 0; mi < 4; mi++) {
                int m0 = wm * 64 + mi * 16;
                u32t a[4];
                a[0] = As[h][m0 + lr][ca];
                a[1] = As[h][m0 + lr + 8][ca];
                a[2] = As[h][m0 + lr][ca ^ 4];
                a[3] = As[h][m0 + lr + 8][ca ^ 4];
#pragma unroll
                for (int ni = 0; ni < 4; ni++) {
                    mma_f16(acc[mi][ni], a, bh[ni]);
                }
            }
        }
        __syncthreads();

        if (kb == 3) {
            // end of X-part: undo the dinv premultiplication of g_fh rows
#pragma unroll
            for (int mi = 0; mi < 4; mi++) {
                int r0 = bm + wm * 64 + mi * 16 + lr;
                int r1 = r0 + 8;
                float s0 = (r0 < n) ? (1.0f / g_dinv[r0]) : 0.f;
                float s1 = (r1 < n) ? (1.0f / g_dinv[r1]) : 0.f;
#pragma unroll
                for (int ni = 0; ni < 4; ni++) {
                    acc[mi][ni][0] *= s0;
                    acc[mi][ni][1] *= s0;
                    acc[mi][ni][2] *= s1;
                    acc[mi][ni][3] *= s1;
                }
            }
        }
    }

    if (layer == 0) {
        // epilogue: g_fh = half(relu(acc+bias) * dinv)
#pragma unroll
        for (int mi = 0; mi < 4; mi++) {
            int r0 = bm + wm * 64 + mi * 16 + lr;
            int r1 = r0 + 8;
            float w0 = (r0 < n) ? g_dinv[r0] : 0.f;
            float w1 = (r1 < n) ? g_dinv[r1] : 0.f;
#pragma unroll
            for (int ni = 0; ni < 4; ni++) {
                int col = wn * 32 + ni * 8 + lc * 2;
                float2 bv = *(const float2*)&bias[col];
                if (r0 < n) {
                    float v0 = fmaxf(acc[mi][ni][0] + bv.x, 0.f);
                    float v1 = fmaxf(acc[mi][ni][1] + bv.y, 0.f);
                    __half2 hh = __floats2half2_rn(v0 * w0, v1 * w0);
                    g_fh[(size_t)r0 * 64 + (col >> 1)] = *(u32t*)&hh;
                }
                if (r1 < n) {
                    float v2 = fmaxf(acc[mi][ni][2] + bv.x, 0.f);
                    float v3 = fmaxf(acc[mi][ni][3] + bv.y, 0.f);
                    __half2 hh = __floats2half2_rn(v2 * w1, v3 * w1);
                    g_fh[(size_t)r1 * 64 + (col >> 1)] = *(u32t*)&hh;
                }
            }
        }
    } else {
        // epilogue: fused segment max (block spans at most 2 graphs: GBM < gsize)
        if (tid < 256) red[tid] = 0u;
        __syncthreads();
        int g0  = bm / gsize;
        int bnd = (g0 + 1) * gsize;
#pragma unroll
        for (int mi = 0; mi < 4; mi++) {
            int r0 = bm + wm * 64 + mi * 16 + lr;
            int r1 = r0 + 8;
#pragma unroll
            for (int ni = 0; ni < 4; ni++) {
                int col = wn * 32 + ni * 8 + lc * 2;
                float2 bv = *(const float2*)&bias[col];
                if (r0 < n) {
                    float v0 = fmaxf(acc[mi][ni][0] + bv.x, 0.f);
                    float v1 = fmaxf(acc[mi][ni][1] + bv.y, 0.f);
                    int s = (r0 >= bnd) ? 128 : 0;
                    atomicMax(&red[s + col], __float_as_uint(v0));
                    atomicMax(&red[s + col + 1], __float_as_uint(v1));
                }
                if (r1 < n) {
                    float v2 = fmaxf(acc[mi][ni][2] + bv.x, 0.f);
                    float v3 = fmaxf(acc[mi][ni][3] + bv.y, 0.f);
                    int s = (r1 >= bnd) ? 128 : 0;
                    atomicMax(&red[s + col], __float_as_uint(v2));
                    atomicMax(&red[s + col + 1], __float_as_uint(v3));
                }
            }
        }
        __syncthreads();
        if (tid < 256) {
            int seg = tid >> 7;
            int c   = tid & 127;
            int g   = g0 + seg;
            bool has = (seg == 0) || (bnd < bm + GBM && bnd < n);
            if (g < nb && has) atomicMax(&g_hg[g * HID + c], red[tid]);
        }
    }
}

// ---------------- classifier head ----------------
__global__ void k_final(const float* __restrict__ Wc, const float* __restrict__ bc,
                        float* __restrict__ out, int nb) {
    int t = blockIdx.x * blockDim.x + threadIdx.x;
    if (t >= nb * 10) return;
    int g = t / 10;
    int c = t % 10;
    float acc = bc[c];
#pragma unroll 8
    for (int k = 0; k < HID; k++)
        acc += __uint_as_float(g_hg[g * HID + k]) * Wc[k * 10 + c];
    out[t] = acc;
}

// ---------------- launch ----------------
extern "C" void kernel_launch(void* const* d_in, const int* in_sizes, int n_in,
                              void* d_out, int out_size) {
    const float* x   = (const float*)d_in[0];
    const float* W1  = (const float*)d_in[1];
    const float* b1  = (const float*)d_in[2];
    const float* W2  = (const float*)d_in[3];
    const float* b2  = (const float*)d_in[4];
    const float* Wc  = (const float*)d_in[5];
    const float* bc  = (const float*)d_in[6];
    const int*   src = (const int*)d_in[7];
    const int*   dst = (const int*)d_in[8];
    float* out = (float*)d_out;

    int e = in_sizes[7];
    int n = in_sizes[9];
    int nb_graphs = out_size / 10;
    int gsize = n / nb_graphs;
    int nbscan = (n + 1023) / 1024;
    int nGemm = (n + GBM - 1) / GBM;

    int histN = (e > 32768 ? e : 32768);
    int fillN = (e > n * 32 ? e : n * 32);

    k_hist<<<(histN + 255) / 256, 256>>>(dst, W1, W2, e);
    k_scanA<<<nbscan, 1024>>>(n);
    k_scanC<<<nbscan, 1024>>>(n, e, nbscan);
    k_fill<<<(fillN + 255) / 256, 256>>>(src, dst, x, e, n);

    // layer 1
    k_spmm<<<(n + 7) / 8, 256>>>(n);
    k_gemm_tc<<<nGemm, 256>>>(0, b1, n, gsize, nb_graphs);
    // layer 2
    k_spmm<<<(n + 7) / 8, 256>>>(n);
    k_gemm_tc<<<nGemm, 256>>>(1, b2, n, gsize, nb_graphs);

    k_final<<<1, 512>>>(Wc, bc, out, nb_graphs);
}